// round 5
// baseline (speedup 1.0000x reference)
#include <cuda_runtime.h>
#include <cuda_bf16.h>
#include <stdint.h>

#define T_SEQ   32768
#define IN_DIM  1024
#define H_DIM   20
#define NLAYER  4
#define G4      80
#define NSTEPS  (T_SEQ + 2 * (NLAYER - 1))

// Layer-0 input projection (both biases folded in). 10.5 MB.
__device__ float g_proj[T_SEQ * G4];

// ---------------------------------------------------------------------------
// Kernel 1: proj[t][g] = b_ih0[g] + b_hh0[g] + x[t] . W_ih0[g]
// ---------------------------------------------------------------------------
__global__ __launch_bounds__(160) void proj_kernel(
    const float* __restrict__ x,
    const float* __restrict__ W,
    const float* __restrict__ bi,
    const float* __restrict__ bh)
{
    __shared__ __align__(16) float xs[8 * IN_DIM];
    const int t0 = blockIdx.x * 8;

    const float4* xg  = (const float4*)(x + (size_t)t0 * IN_DIM);
    float4*       xs4 = (float4*)xs;
    for (int i = threadIdx.x; i < 8 * (IN_DIM / 4); i += blockDim.x)
        xs4[i] = xg[i];
    __syncthreads();

    const int tid = threadIdx.x;
    if (tid >= 160) return;
    const int g  = tid % 80;
    const int th = tid / 80;

    const float4* Wg = (const float4*)(W + (size_t)g * IN_DIM);
    float a0 = 0.f, a1 = 0.f, a2 = 0.f, a3 = 0.f;

    #pragma unroll 4
    for (int kk = 0; kk < IN_DIM / 4; ++kk) {
        float4 w4 = Wg[kk];
        float4 v0 = xs4[(th * 4 + 0) * (IN_DIM / 4) + kk];
        float4 v1 = xs4[(th * 4 + 1) * (IN_DIM / 4) + kk];
        float4 v2 = xs4[(th * 4 + 2) * (IN_DIM / 4) + kk];
        float4 v3 = xs4[(th * 4 + 3) * (IN_DIM / 4) + kk];
        a0 = fmaf(w4.x, v0.x, a0); a0 = fmaf(w4.y, v0.y, a0);
        a0 = fmaf(w4.z, v0.z, a0); a0 = fmaf(w4.w, v0.w, a0);
        a1 = fmaf(w4.x, v1.x, a1); a1 = fmaf(w4.y, v1.y, a1);
        a1 = fmaf(w4.z, v1.z, a1); a1 = fmaf(w4.w, v1.w, a1);
        a2 = fmaf(w4.x, v2.x, a2); a2 = fmaf(w4.y, v2.y, a2);
        a2 = fmaf(w4.z, v2.z, a2); a2 = fmaf(w4.w, v2.w, a2);
        a3 = fmaf(w4.x, v3.x, a3); a3 = fmaf(w4.y, v3.y, a3);
        a3 = fmaf(w4.z, v3.z, a3); a3 = fmaf(w4.w, v3.w, a3);
    }

    const float b = bi[g] + bh[g];
    const int tb = t0 + th * 4;
    g_proj[(size_t)(tb + 0) * G4 + g] = a0 + b;
    g_proj[(size_t)(tb + 1) * G4 + g] = a1 + b;
    g_proj[(size_t)(tb + 2) * G4 + g] = a2 + b;
    g_proj[(size_t)(tb + 3) * G4 + g] = a3 + b;
}

// ---------------------------------------------------------------------------
__device__ __forceinline__ unsigned long long fma2(
    unsigned long long a, unsigned long long b, unsigned long long c)
{
    unsigned long long d;
    asm("fma.rn.f32x2 %0, %1, %2, %3;" : "=l"(d) : "l"(a), "l"(b), "l"(c));
    return d;
}
__device__ __forceinline__ float lo32(unsigned long long u) {
    return __uint_as_float((unsigned)u);
}
__device__ __forceinline__ float hi32(unsigned long long u) {
    return __uint_as_float((unsigned)(u >> 32));
}
__device__ __forceinline__ float tanh_fast(float x) {
    float y;
    asm("tanh.approx.f32 %0, %1;" : "=f"(y) : "f"(x));
    return y;
}
__device__ __forceinline__ float sig_fast(float x) {
    return fmaf(tanh_fast(0.5f * x), 0.5f, 0.5f);
}

// ---------------------------------------------------------------------------
// Kernel 2: single block, 512 threads. Warp group (4 warps) per layer.
// Warp wl of layer l owns gate rows [20*wl, 20*wl+20); lane j<20 = one row.
// Layer l at step s processes t = s - 2l (2-step skew => one barrier/step).
// Cross-layer h via 4-deep smem ring; own-h + operand vector rebuilt with
// replicated identical writes per layer (benign races) + __syncwarp.
// ---------------------------------------------------------------------------
__global__ __launch_bounds__(512, 1) void rnn_kernel(
    const float* __restrict__ W_hh0,   // [80][20]
    const float* __restrict__ W_ih_r,  // [3][80][20]
    const float* __restrict__ W_hh_r,  // [3][80][20]
    const float* __restrict__ b_ih_r,  // [3][80]
    const float* __restrict__ b_hh_r,  // [3][80]
    const float* __restrict__ lin_w,   // [20]
    const float* __restrict__ lin_b,   // [1]
    float* __restrict__ out)
{
    const int tid = threadIdx.x;
    const int wid = tid >> 5;
    const int l   = wid >> 2;          // layer
    const int wl  = wid & 3;           // gate group: 0=i 1=f 2=g 3=o
    const int j   = tid & 31;
    const bool act_lane = (j < H_DIM);

    // v[p][l][0..19] = h_{l-1}(t), v[p][l][20..39] = h_l(t-1)
    __shared__ __align__(16) float v[2][NLAYER][40];
    __shared__ float acts[2][NLAYER][4][24];
    __shared__ float hring[4][NLAYER][24];   // hring[s&3][l] = h_l at its step s

    for (int i = tid; i < 2 * NLAYER * 40; i += blockDim.x)
        ((float*)v)[i] = 0.f;
    for (int i = tid; i < 4 * NLAYER * 24; i += blockDim.x)
        ((float*)hring)[i] = 0.f;

    // --- per-lane weights: row = 20*wl + j (lanes >=20 dup row 19) ---
    const int row = wl * H_DIM + (act_lane ? j : H_DIM - 1);
    unsigned long long wv[20];
    float bias = 0.f;
    if (l > 0)
        bias = b_ih_r[(l - 1) * G4 + row] + b_hh_r[(l - 1) * G4 + row];
    #pragma unroll
    for (int kk = 0; kk < 10; ++kk) {   // input-h part (zero for layer 0)
        float flo = 0.f, fhi = 0.f;
        if (l > 0) {
            flo = W_ih_r[(l - 1) * 1600 + row * H_DIM + 2 * kk];
            fhi = W_ih_r[(l - 1) * 1600 + row * H_DIM + 2 * kk + 1];
        }
        wv[kk] = (unsigned long long)__float_as_uint(flo) |
                 ((unsigned long long)__float_as_uint(fhi) << 32);
    }
    #pragma unroll
    for (int kk = 0; kk < 10; ++kk) {   // own-h part
        float flo, fhi;
        if (l == 0) {
            flo = W_hh0[row * H_DIM + 2 * kk];
            fhi = W_hh0[row * H_DIM + 2 * kk + 1];
        } else {
            flo = W_hh_r[(l - 1) * 1600 + row * H_DIM + 2 * kk];
            fhi = W_hh_r[(l - 1) * 1600 + row * H_DIM + 2 * kk + 1];
        }
        wv[10 + kk] = (unsigned long long)__float_as_uint(flo) |
                      ((unsigned long long)__float_as_uint(fhi) << 32);
    }
    const float lw = act_lane ? lin_w[j] : 0.f;
    const float lb = lin_b[0];

    float c = 0.f;
    float pp0 = 0.f, pp1 = 0.f;        // layer-0 pre(t), pre(t+1)
    if (l == 0) {
        pp0 = __ldg(&g_proj[row]);
        pp1 = __ldg(&g_proj[G4 + row]);
    }
    __syncthreads();

    const unsigned FULL = 0xffffffffu;

    for (int s = 0; s < NSTEPS; ++s) {
        const int t = s - 2 * l;
        const int p = s & 1;
        const bool active = (t >= 0) && (t < T_SEQ);

        if (active) {
            float pre = (l == 0) ? pp0 : bias;
            unsigned long long a0 = 0ull, a1 = 0ull;
            const ulonglong2* vp = (const ulonglong2*)&v[p][l][0];
            #pragma unroll
            for (int q = 0; q < 5; ++q) {
                ulonglong2 va = vp[q];          // input-h pairs
                ulonglong2 vb = vp[5 + q];      // own-h pairs
                a0 = fma2(wv[2 * q],      va.x, a0);
                a1 = fma2(wv[2 * q + 1],  va.y, a1);
                a0 = fma2(wv[10 + 2 * q], vb.x, a0);
                a1 = fma2(wv[11 + 2 * q], vb.y, a1);
            }
            float g = pre + (lo32(a0) + hi32(a0)) + (lo32(a1) + hi32(a1));
            float act = (wl == 2) ? tanh_fast(g) : sig_fast(g);
            if (act_lane) acts[p][l][wl][j] = act;
        }
        __syncthreads();

        // assemble next step's input-h from the ring (always; stale writes
        // are never read — activity windows are disjoint at the boundaries)
        if (act_lane && l > 0)
            v[p ^ 1][l][j] = hring[(s + 3) & 3][l - 1][j];

        float hnew = 0.f;
        if (active) {
            if (act_lane) {
                float ai = acts[p][l][0][j];
                float af = acts[p][l][1][j];
                float ag = acts[p][l][2][j];
                float ao = acts[p][l][3][j];
                c = fmaf(af, c, ai * ag);
                hnew = ao * tanh_fast(c);
                v[p ^ 1][l][20 + j] = hnew;
                if (l < 3) hring[s & 3][l][j] = hnew;
            }
            if (l == 0) {
                pp0 = pp1;
                const int tp = t + 2;
                if (tp < T_SEQ) pp1 = __ldg(&g_proj[(size_t)tp * G4 + row]);
            }
            if (l == 3 && wl == 0 && t == T_SEQ - 1) {
                float part = hnew * lw;    // lw = 0 for lanes >= 20
                #pragma unroll
                for (int off = 16; off; off >>= 1)
                    part += __shfl_xor_sync(FULL, part, off);
                if (j == 0) out[0] = sig_fast(part + lb);
            }
        }
        __syncwarp();   // order own v/ring STS before next step's LDS
    }
}

// ---------------------------------------------------------------------------
extern "C" void kernel_launch(void* const* d_in, const int* in_sizes, int n_in,
                              void* d_out, int out_size)
{
    const float* x      = (const float*)d_in[0];
    const float* W_ih0  = (const float*)d_in[1];
    const float* W_hh0  = (const float*)d_in[2];
    const float* b_ih0  = (const float*)d_in[3];
    const float* b_hh0  = (const float*)d_in[4];
    const float* W_ih_r = (const float*)d_in[5];
    const float* W_hh_r = (const float*)d_in[6];
    const float* b_ih_r = (const float*)d_in[7];
    const float* b_hh_r = (const float*)d_in[8];
    const float* lin_w  = (const float*)d_in[9];
    const float* lin_b  = (const float*)d_in[10];

    proj_kernel<<<T_SEQ / 8, 160>>>(x, W_ih0, b_ih0, b_hh0);
    rnn_kernel<<<1, 512>>>(W_hh0, W_ih_r, W_hh_r, b_ih_r, b_hh_r,
                           lin_w, lin_b, (float*)d_out);
}

// round 7
// speedup vs baseline: 1.4153x; 1.4153x over previous
#include <cuda_runtime.h>
#include <cuda_bf16.h>
#include <stdint.h>

#define T_SEQ   32768
#define IN_DIM  1024
#define H_DIM   20
#define NLAYER  4
#define G4      80
#define NSTEPS  (T_SEQ + 2 * (NLAYER - 1))

// Layer-0 input projection (both biases folded in). 10.5 MB.
__device__ float g_proj[T_SEQ * G4];

// ---------------------------------------------------------------------------
// Kernel 1: proj[t][g] = b_ih0[g] + b_hh0[g] + x[t] . W_ih0[g]
// ---------------------------------------------------------------------------
__global__ __launch_bounds__(160) void proj_kernel(
    const float* __restrict__ x,
    const float* __restrict__ W,
    const float* __restrict__ bi,
    const float* __restrict__ bh)
{
    __shared__ __align__(16) float xs[8 * IN_DIM];
    const int t0 = blockIdx.x * 8;

    const float4* xg  = (const float4*)(x + (size_t)t0 * IN_DIM);
    float4*       xs4 = (float4*)xs;
    for (int i = threadIdx.x; i < 8 * (IN_DIM / 4); i += blockDim.x)
        xs4[i] = xg[i];
    __syncthreads();

    const int tid = threadIdx.x;
    if (tid >= 160) return;
    const int g  = tid % 80;
    const int th = tid / 80;

    const float4* Wg = (const float4*)(W + (size_t)g * IN_DIM);
    float a0 = 0.f, a1 = 0.f, a2 = 0.f, a3 = 0.f;

    #pragma unroll 4
    for (int kk = 0; kk < IN_DIM / 4; ++kk) {
        float4 w4 = Wg[kk];
        float4 v0 = xs4[(th * 4 + 0) * (IN_DIM / 4) + kk];
        float4 v1 = xs4[(th * 4 + 1) * (IN_DIM / 4) + kk];
        float4 v2 = xs4[(th * 4 + 2) * (IN_DIM / 4) + kk];
        float4 v3 = xs4[(th * 4 + 3) * (IN_DIM / 4) + kk];
        a0 = fmaf(w4.x, v0.x, a0); a0 = fmaf(w4.y, v0.y, a0);
        a0 = fmaf(w4.z, v0.z, a0); a0 = fmaf(w4.w, v0.w, a0);
        a1 = fmaf(w4.x, v1.x, a1); a1 = fmaf(w4.y, v1.y, a1);
        a1 = fmaf(w4.z, v1.z, a1); a1 = fmaf(w4.w, v1.w, a1);
        a2 = fmaf(w4.x, v2.x, a2); a2 = fmaf(w4.y, v2.y, a2);
        a2 = fmaf(w4.z, v2.z, a2); a2 = fmaf(w4.w, v2.w, a2);
        a3 = fmaf(w4.x, v3.x, a3); a3 = fmaf(w4.y, v3.y, a3);
        a3 = fmaf(w4.z, v3.z, a3); a3 = fmaf(w4.w, v3.w, a3);
    }

    const float b = bi[g] + bh[g];
    const int tb = t0 + th * 4;
    g_proj[(size_t)(tb + 0) * G4 + g] = a0 + b;
    g_proj[(size_t)(tb + 1) * G4 + g] = a1 + b;
    g_proj[(size_t)(tb + 2) * G4 + g] = a2 + b;
    g_proj[(size_t)(tb + 3) * G4 + g] = a3 + b;
}

// ---------------------------------------------------------------------------
__device__ __forceinline__ unsigned long long fma2(
    unsigned long long a, unsigned long long b, unsigned long long c)
{
    unsigned long long d;
    asm("fma.rn.f32x2 %0, %1, %2, %3;" : "=l"(d) : "l"(a), "l"(b), "l"(c));
    return d;
}
__device__ __forceinline__ float lo32(unsigned long long u) {
    return __uint_as_float((unsigned)u);
}
__device__ __forceinline__ float hi32(unsigned long long u) {
    return __uint_as_float((unsigned)(u >> 32));
}
__device__ __forceinline__ unsigned long long pack1(float lo) {
    return (unsigned long long)__float_as_uint(lo);   // (lo, 0.0f)
}
__device__ __forceinline__ float tanh_fast(float x) {
    float y;
    asm("tanh.approx.f32 %0, %1;" : "=f"(y) : "f"(x));
    return y;
}
__device__ __forceinline__ float sig_fast(float x) {
    return fmaf(tanh_fast(0.5f * x), 0.5f, 0.5f);
}

// ---------------------------------------------------------------------------
// Kernel 2: single block, 256 threads = 8 warps.
//   warps 0..3  (mains):  layer l = wid; lane j<20 computes unit j's FOUR
//                         gates' own-h dot (4x10 fma2) -> no transpose.
//   warps 4..7  (helpers): layer hl = wid-4; at iter s precompute
//                         pre_l(t') = bias + W_ih . h_{l-1}(t'), t' = s+1-2hl.
//                         helper 0 instead prefetches g_proj rows.
// Layer l processes t = s - 2l. All cross-warp traffic is parity double-
// buffered and ordered by ONE __syncthreads per iteration.
// ---------------------------------------------------------------------------
__global__ __launch_bounds__(256, 1) void rnn_kernel(
    const float* __restrict__ W_hh0,   // [80][20]
    const float* __restrict__ W_ih_r,  // [3][80][20]
    const float* __restrict__ W_hh_r,  // [3][80][20]
    const float* __restrict__ b_ih_r,  // [3][80]
    const float* __restrict__ b_hh_r,  // [3][80]
    const float* __restrict__ lin_w,   // [20]
    const float* __restrict__ lin_b,   // [1]
    float* __restrict__ out)
{
    const int tid = threadIdx.x;
    const int wid = tid >> 5;
    const int j   = tid & 31;
    const int jj  = (j < H_DIM) ? j : H_DIM - 1;   // clamp for dummy lanes
    const bool lane20 = (j < H_DIM);

    // pre[p][l][unit][gate] : float4 per unit -> one LDS.128 on main side
    __shared__ __align__(16) float pre[2][NLAYER][H_DIM][4];
    // own-h double buffer per layer (padded rows, 16B aligned)
    __shared__ __align__(16) float hb[2][NLAYER][24];
    // cross-layer handoff h_l(t), written by main l, read by helper l+1
    __shared__ __align__(16) float hx[2][NLAYER][24];

    for (int i = tid; i < 2 * NLAYER * 24; i += blockDim.x) {
        ((float*)hb)[i] = 0.f;
        ((float*)hx)[i] = 0.f;
    }

    const bool is_main = (wid < NLAYER);
    const int  l       = is_main ? wid : (wid - NLAYER);   // layer id

    // ---- per-lane weights: 4 gate rows (jj, 20+jj, 40+jj, 60+jj) ----
    // mains: W_hh part; helpers (l>0): W_ih part + bias
    unsigned long long wv[4][10];
    float bias4[4] = {0.f, 0.f, 0.f, 0.f};
    #pragma unroll
    for (int g = 0; g < 4; ++g) {
        const int row = g * H_DIM + jj;
        const float* Wsrc;
        if (is_main)
            Wsrc = (l == 0) ? (W_hh0 + row * H_DIM)
                            : (W_hh_r + (l - 1) * 1600 + row * H_DIM);
        else
            Wsrc = (l > 0) ? (W_ih_r + (l - 1) * 1600 + row * H_DIM)
                           : (W_hh0 + row * H_DIM);   // dummy for helper 0
        #pragma unroll
        for (int kk = 0; kk < 10; ++kk) {
            float flo = Wsrc[2 * kk];
            float fhi = Wsrc[2 * kk + 1];
            wv[g][kk] = (unsigned long long)__float_as_uint(flo) |
                        ((unsigned long long)__float_as_uint(fhi) << 32);
        }
        if (!is_main && l > 0)
            bias4[g] = b_ih_r[(l - 1) * G4 + row] + b_hh_r[(l - 1) * G4 + row];
    }
    const float lw = lane20 ? lin_w[jj] : 0.f;
    const float lb = lin_b[0];

    // ---- helper-0 prologue: pre(0) for layer 0 + distance-2 prefetch ----
    float4 pg0 = make_float4(0.f, 0.f, 0.f, 0.f);   // for t' = s+1
    float4 pg1 = make_float4(0.f, 0.f, 0.f, 0.f);   // for t' = s+2
    if (!is_main && l == 0 && lane20) {
        pre[0][0][jj][0] = __ldg(&g_proj[jj]);
        pre[0][0][jj][1] = __ldg(&g_proj[20 + jj]);
        pre[0][0][jj][2] = __ldg(&g_proj[40 + jj]);
        pre[0][0][jj][3] = __ldg(&g_proj[60 + jj]);
        pg0.x = __ldg(&g_proj[1 * G4 + jj]);
        pg0.y = __ldg(&g_proj[1 * G4 + 20 + jj]);
        pg0.z = __ldg(&g_proj[1 * G4 + 40 + jj]);
        pg0.w = __ldg(&g_proj[1 * G4 + 60 + jj]);
        pg1.x = __ldg(&g_proj[2 * G4 + jj]);
        pg1.y = __ldg(&g_proj[2 * G4 + 20 + jj]);
        pg1.z = __ldg(&g_proj[2 * G4 + 40 + jj]);
        pg1.w = __ldg(&g_proj[2 * G4 + 60 + jj]);
    }
    float c = 0.f;
    __syncthreads();

    const unsigned FULL = 0xffffffffu;

    for (int s = 0; s < NSTEPS; ++s) {
        const int p = s & 1;

        if (is_main) {
            const int t = s - 2 * l;
            if (t >= 0 && t < T_SEQ) {
                const float4 pr = *(const float4*)&pre[p][l][jj][0];
                unsigned long long a0 = pack1(pr.x);
                unsigned long long a1 = pack1(pr.y);
                unsigned long long a2 = pack1(pr.z);
                unsigned long long a3 = pack1(pr.w);
                const ulonglong2* vp = (const ulonglong2*)&hb[p][l][0];
                #pragma unroll
                for (int q = 0; q < 5; ++q) {
                    ulonglong2 vv = vp[q];
                    a0 = fma2(wv[0][2*q], vv.x, a0);
                    a1 = fma2(wv[1][2*q], vv.x, a1);
                    a2 = fma2(wv[2][2*q], vv.x, a2);
                    a3 = fma2(wv[3][2*q], vv.x, a3);
                    a0 = fma2(wv[0][2*q+1], vv.y, a0);
                    a1 = fma2(wv[1][2*q+1], vv.y, a1);
                    a2 = fma2(wv[2][2*q+1], vv.y, a2);
                    a3 = fma2(wv[3][2*q+1], vv.y, a3);
                }
                float fi = sig_fast (lo32(a0) + hi32(a0));
                float ff = sig_fast (lo32(a1) + hi32(a1));
                float fg = tanh_fast(lo32(a2) + hi32(a2));
                float fo = sig_fast (lo32(a3) + hi32(a3));
                c = fmaf(ff, c, fi * fg);
                float h = fo * tanh_fast(c);

                if (lane20) {
                    hb[p ^ 1][l][j] = h;      // own h for next step
                    if (l < 3) hx[p][l][j] = h;  // for helper l+1 next iter
                }
                if (l == 3 && t == T_SEQ - 1) {
                    float part = lane20 ? h * lw : 0.f;
                    #pragma unroll
                    for (int off = 16; off; off >>= 1)
                        part += __shfl_xor_sync(FULL, part, off);
                    if (j == 0) out[0] = sig_fast(part + lb);
                }
            }
        } else if (l == 0) {
            // helper 0: stage pre(t'=s+1) from prefetched regs, prefetch t'+2
            const int tp = s + 1;
            if (tp < T_SEQ) {
                if (lane20) *(float4*)&pre[p ^ 1][0][jj][0] = pg0;
                pg0 = pg1;
                const int tf = tp + 2;
                if (tf < T_SEQ && lane20) {
                    pg1.x = __ldg(&g_proj[(size_t)tf * G4 + jj]);
                    pg1.y = __ldg(&g_proj[(size_t)tf * G4 + 20 + jj]);
                    pg1.z = __ldg(&g_proj[(size_t)tf * G4 + 40 + jj]);
                    pg1.w = __ldg(&g_proj[(size_t)tf * G4 + 60 + jj]);
                }
            }
        } else {
            // helper l>0: pre_l(t') = bias + W_ih . h_{l-1}(t'), t' = s+1-2l
            const int tp = s + 1 - 2 * l;
            if (tp >= 0 && tp < T_SEQ) {
                unsigned long long a0 = pack1(bias4[0]);
                unsigned long long a1 = pack1(bias4[1]);
                unsigned long long a2 = pack1(bias4[2]);
                unsigned long long a3 = pack1(bias4[3]);
                const ulonglong2* vp = (const ulonglong2*)&hx[p ^ 1][l - 1][0];
                #pragma unroll
                for (int q = 0; q < 5; ++q) {
                    ulonglong2 vv = vp[q];
                    a0 = fma2(wv[0][2*q], vv.x, a0);
                    a1 = fma2(wv[1][2*q], vv.x, a1);
                    a2 = fma2(wv[2][2*q], vv.x, a2);
                    a3 = fma2(wv[3][2*q], vv.x, a3);
                    a0 = fma2(wv[0][2*q+1], vv.y, a0);
                    a1 = fma2(wv[1][2*q+1], vv.y, a1);
                    a2 = fma2(wv[2][2*q+1], vv.y, a2);
                    a3 = fma2(wv[3][2*q+1], vv.y, a3);
                }
                if (lane20) {
                    float4 pr;
                    pr.x = lo32(a0) + hi32(a0);
                    pr.y = lo32(a1) + hi32(a1);
                    pr.z = lo32(a2) + hi32(a2);
                    pr.w = lo32(a3) + hi32(a3);
                    *(float4*)&pre[p ^ 1][l][jj][0] = pr;
                }
            }
        }

        __syncthreads();   // orders ALL smem handoff (pre, hb, hx) block-wide
    }
}

// ---------------------------------------------------------------------------
extern "C" void kernel_launch(void* const* d_in, const int* in_sizes, int n_in,
                              void* d_out, int out_size)
{
    const float* x      = (const float*)d_in[0];
    const float* W_ih0  = (const float*)d_in[1];
    const float* W_hh0  = (const float*)d_in[2];
    const float* b_ih0  = (const float*)d_in[3];
    const float* b_hh0  = (const float*)d_in[4];
    const float* W_ih_r = (const float*)d_in[5];
    const float* W_hh_r = (const float*)d_in[6];
    const float* b_ih_r = (const float*)d_in[7];
    const float* b_hh_r = (const float*)d_in[8];
    const float* lin_w  = (const float*)d_in[9];
    const float* lin_b  = (const float*)d_in[10];

    proj_kernel<<<T_SEQ / 8, 160>>>(x, W_ih0, b_ih0, b_hh0);
    rnn_kernel<<<1, 256>>>(W_hh0, W_ih_r, W_hh_r, b_ih_r, b_hh_r,
                           lin_w, lin_b, (float*)d_out);
}

// round 8
// speedup vs baseline: 2.4527x; 1.7329x over previous
#include <cuda_runtime.h>
#include <cuda_bf16.h>
#include <stdint.h>

#define T_SEQ   32768
#define IN_DIM  1024
#define H_DIM   20
#define NLAYER  4
#define G4      80
#define KSTEP   8
#define NB      (T_SEQ / KSTEP)
#define NPHASE  (NB + 6)

// Layer-0 input projection, layout [t][unit][gate] (both biases folded). 10.5 MB
__device__ float g_proj[T_SEQ * G4];

// ---------------------------------------------------------------------------
// Kernel 1: proj = x @ W_ih0^T + b_ih0 + b_hh0, stored [t][unit*4 + gate]
// ---------------------------------------------------------------------------
__global__ __launch_bounds__(160) void proj_kernel(
    const float* __restrict__ x,
    const float* __restrict__ W,
    const float* __restrict__ bi,
    const float* __restrict__ bh)
{
    __shared__ __align__(16) float xs[8 * IN_DIM];
    const int t0 = blockIdx.x * 8;

    const float4* xg  = (const float4*)(x + (size_t)t0 * IN_DIM);
    float4*       xs4 = (float4*)xs;
    for (int i = threadIdx.x; i < 8 * (IN_DIM / 4); i += blockDim.x)
        xs4[i] = xg[i];
    __syncthreads();

    const int tid = threadIdx.x;
    if (tid >= 160) return;
    const int g  = tid % 80;            // weight row: gate = g/20, unit = g%20
    const int th = tid / 80;
    const int didx = (g % 20) * 4 + (g / 20);   // dest offset within row

    const float4* Wg = (const float4*)(W + (size_t)g * IN_DIM);
    float a0 = 0.f, a1 = 0.f, a2 = 0.f, a3 = 0.f;

    #pragma unroll 4
    for (int kk = 0; kk < IN_DIM / 4; ++kk) {
        float4 w4 = Wg[kk];
        float4 v0 = xs4[(th * 4 + 0) * (IN_DIM / 4) + kk];
        float4 v1 = xs4[(th * 4 + 1) * (IN_DIM / 4) + kk];
        float4 v2 = xs4[(th * 4 + 2) * (IN_DIM / 4) + kk];
        float4 v3 = xs4[(th * 4 + 3) * (IN_DIM / 4) + kk];
        a0 = fmaf(w4.x, v0.x, a0); a0 = fmaf(w4.y, v0.y, a0);
        a0 = fmaf(w4.z, v0.z, a0); a0 = fmaf(w4.w, v0.w, a0);
        a1 = fmaf(w4.x, v1.x, a1); a1 = fmaf(w4.y, v1.y, a1);
        a1 = fmaf(w4.z, v1.z, a1); a1 = fmaf(w4.w, v1.w, a1);
        a2 = fmaf(w4.x, v2.x, a2); a2 = fmaf(w4.y, v2.y, a2);
        a2 = fmaf(w4.z, v2.z, a2); a2 = fmaf(w4.w, v2.w, a2);
        a3 = fmaf(w4.x, v3.x, a3); a3 = fmaf(w4.y, v3.y, a3);
        a3 = fmaf(w4.z, v3.z, a3); a3 = fmaf(w4.w, v3.w, a3);
    }

    const float b = bi[g] + bh[g];
    const int tb = t0 + th * 4;
    g_proj[(size_t)(tb + 0) * G4 + didx] = a0 + b;
    g_proj[(size_t)(tb + 1) * G4 + didx] = a1 + b;
    g_proj[(size_t)(tb + 2) * G4 + didx] = a2 + b;
    g_proj[(size_t)(tb + 3) * G4 + didx] = a3 + b;
}

// ---------------------------------------------------------------------------
__device__ __forceinline__ unsigned long long fma2(
    unsigned long long a, unsigned long long b, unsigned long long c)
{
    unsigned long long d;
    asm("fma.rn.f32x2 %0, %1, %2, %3;" : "=l"(d) : "l"(a), "l"(b), "l"(c));
    return d;
}
__device__ __forceinline__ unsigned long long add2(
    unsigned long long a, unsigned long long b)
{
    unsigned long long d;
    asm("add.rn.f32x2 %0, %1, %2;" : "=l"(d) : "l"(a), "l"(b));
    return d;
}
__device__ __forceinline__ float lo32(unsigned long long u) {
    return __uint_as_float((unsigned)u);
}
__device__ __forceinline__ float hi32(unsigned long long u) {
    return __uint_as_float((unsigned)(u >> 32));
}
__device__ __forceinline__ unsigned long long pack1(float lo) {
    return (unsigned long long)__float_as_uint(lo);   // (lo, 0.0f)
}
__device__ __forceinline__ float tanh_fast(float x) {
    float y;
    asm("tanh.approx.f32 %0, %1;" : "=f"(y) : "f"(x));
    return y;
}
__device__ __forceinline__ float sig_fast(float x) {
    return fmaf(tanh_fast(0.5f * x), 0.5f, 0.5f);
}

// ---------------------------------------------------------------------------
// Kernel 2: block-pipelined. 256 threads = 8 warps.
//  mains   wid 0..3: layer l = wid; at phase k process block b = k - 2l
//          (K=8 steps, own-h recurrence warp-local, no block barrier inside).
//  helpers wid 4..7: helper l; at phase k produce pre for block k+1-2l
//          (l>0: bias + W_ih . h_{l-1} from hx; l=0: stage g_proj rows).
// ONE __syncthreads per phase orders all pre/hx handoff (parity buffers).
// ---------------------------------------------------------------------------
__global__ __launch_bounds__(256, 1) void rnn_kernel(
    const float* __restrict__ W_hh0,   // [80][20]
    const float* __restrict__ W_ih_r,  // [3][80][20]
    const float* __restrict__ W_hh_r,  // [3][80][20]
    const float* __restrict__ b_ih_r,  // [3][80]
    const float* __restrict__ b_hh_r,  // [3][80]
    const float* __restrict__ lin_w,   // [20]
    const float* __restrict__ lin_b,   // [1]
    float* __restrict__ out)
{
    const int tid = threadIdx.x;
    const int wid = tid >> 5;
    const int j   = tid & 31;
    const int jj  = (j < H_DIM) ? j : H_DIM - 1;
    const bool lane20 = (j < H_DIM);

    __shared__ __align__(16) float pre[2][NLAYER][KSTEP][H_DIM][4];
    __shared__ __align__(16) float hx [2][NLAYER][KSTEP][24];
    __shared__ __align__(16) float hb [NLAYER][24];

    for (int i = tid; i < NLAYER * 24; i += blockDim.x)
        ((float*)hb)[i] = 0.f;

    const bool is_main = (wid < NLAYER);
    const int  l       = wid & 3;

    // ---- per-lane weights: 4 gate rows (jj, 20+jj, 40+jj, 60+jj) ----
    unsigned long long wv[4][10];
    float bias4[4] = {0.f, 0.f, 0.f, 0.f};
    #pragma unroll
    for (int g = 0; g < 4; ++g) {
        const int row = g * H_DIM + jj;
        const float* Wsrc;
        if (is_main)
            Wsrc = (l == 0) ? (W_hh0 + row * H_DIM)
                            : (W_hh_r + (l - 1) * 1600 + row * H_DIM);
        else
            Wsrc = (l > 0) ? (W_ih_r + (l - 1) * 1600 + row * H_DIM)
                           : (W_hh0 + row * H_DIM);   // dummy for helper 0
        #pragma unroll
        for (int kk = 0; kk < 10; ++kk) {
            float flo = Wsrc[2 * kk];
            float fhi = Wsrc[2 * kk + 1];
            wv[g][kk] = (unsigned long long)__float_as_uint(flo) |
                        ((unsigned long long)__float_as_uint(fhi) << 32);
        }
        if (!is_main && l > 0)
            bias4[g] = b_ih_r[(l - 1) * G4 + row] + b_hh_r[(l - 1) * G4 + row];
    }
    const float lw = lane20 ? lin_w[jj] : 0.f;
    const float lb = lin_b[0];

    const float4* gp4 = (const float4*)g_proj;   // [t][20 float4]

    // ---- prologue: helper 0 stages block 0 into pre[parity 0] ----
    if (!is_main && l == 0 && lane20) {
        #pragma unroll
        for (int i = 0; i < KSTEP; ++i) {
            float4 v = __ldg(&gp4[(size_t)i * H_DIM + jj]);
            *(float4*)&pre[0][0][i][jj][0] = v;
        }
    }
    float c = 0.f;
    float hlast = 0.f;
    __syncthreads();

    const unsigned FULL = 0xffffffffu;

    for (int k = 0; k < NPHASE; ++k) {
        const int p = k & 1;

        if (is_main) {
            const int b = k - 2 * l;
            if (b >= 0 && b < NB) {
                #pragma unroll
                for (int i = 0; i < KSTEP; ++i) {
                    __syncwarp();
                    const float4 pr = *(const float4*)&pre[p][l][i][jj][0];
                    const ulonglong2* vp = (const ulonglong2*)&hb[l][0];
                    ulonglong2 v0 = vp[0], v1 = vp[1], v2 = vp[2],
                               v3 = vp[3], v4 = vp[4];
                    unsigned long long a0x = pack1(pr.x), a0y = 0ull;
                    unsigned long long a1x = pack1(pr.y), a1y = 0ull;
                    unsigned long long a2x = pack1(pr.z), a2y = 0ull;
                    unsigned long long a3x = pack1(pr.w), a3y = 0ull;
                    a0x = fma2(wv[0][0], v0.x, a0x); a0y = fma2(wv[0][1], v0.y, a0y);
                    a1x = fma2(wv[1][0], v0.x, a1x); a1y = fma2(wv[1][1], v0.y, a1y);
                    a2x = fma2(wv[2][0], v0.x, a2x); a2y = fma2(wv[2][1], v0.y, a2y);
                    a3x = fma2(wv[3][0], v0.x, a3x); a3y = fma2(wv[3][1], v0.y, a3y);
                    a0x = fma2(wv[0][2], v1.x, a0x); a0y = fma2(wv[0][3], v1.y, a0y);
                    a1x = fma2(wv[1][2], v1.x, a1x); a1y = fma2(wv[1][3], v1.y, a1y);
                    a2x = fma2(wv[2][2], v1.x, a2x); a2y = fma2(wv[2][3], v1.y, a2y);
                    a3x = fma2(wv[3][2], v1.x, a3x); a3y = fma2(wv[3][3], v1.y, a3y);
                    a0x = fma2(wv[0][4], v2.x, a0x); a0y = fma2(wv[0][5], v2.y, a0y);
                    a1x = fma2(wv[1][4], v2.x, a1x); a1y = fma2(wv[1][5], v2.y, a1y);
                    a2x = fma2(wv[2][4], v2.x, a2x); a2y = fma2(wv[2][5], v2.y, a2y);
                    a3x = fma2(wv[3][4], v2.x, a3x); a3y = fma2(wv[3][5], v2.y, a3y);
                    a0x = fma2(wv[0][6], v3.x, a0x); a0y = fma2(wv[0][7], v3.y, a0y);
                    a1x = fma2(wv[1][6], v3.x, a1x); a1y = fma2(wv[1][7], v3.y, a1y);
                    a2x = fma2(wv[2][6], v3.x, a2x); a2y = fma2(wv[2][7], v3.y, a2y);
                    a3x = fma2(wv[3][6], v3.x, a3x); a3y = fma2(wv[3][7], v3.y, a3y);
                    a0x = fma2(wv[0][8], v4.x, a0x); a0y = fma2(wv[0][9], v4.y, a0y);
                    a1x = fma2(wv[1][8], v4.x, a1x); a1y = fma2(wv[1][9], v4.y, a1y);
                    a2x = fma2(wv[2][8], v4.x, a2x); a2y = fma2(wv[2][9], v4.y, a2y);
                    a3x = fma2(wv[3][8], v4.x, a3x); a3y = fma2(wv[3][9], v4.y, a3y);
                    unsigned long long s0 = add2(a0x, a0y);
                    unsigned long long s1 = add2(a1x, a1y);
                    unsigned long long s2 = add2(a2x, a2y);
                    unsigned long long s3 = add2(a3x, a3y);
                    float fi = sig_fast (lo32(s0) + hi32(s0));
                    float ff = sig_fast (lo32(s1) + hi32(s1));
                    float fg = tanh_fast(lo32(s2) + hi32(s2));
                    float fo = sig_fast (lo32(s3) + hi32(s3));
                    c = fmaf(ff, c, fi * fg);
                    float h = fo * tanh_fast(c);
                    hlast = h;
                    if (lane20) {
                        hb[l][j] = h;
                        if (l < 3) hx[p][l][i][j] = h;
                    }
                }
                if (l == 3 && b == NB - 1) {
                    float part = hlast * lw;   // lw = 0 for lanes >= 20
                    #pragma unroll
                    for (int off = 16; off; off >>= 1)
                        part += __shfl_xor_sync(FULL, part, off);
                    if (j == 0) out[0] = sig_fast(part + lb);
                }
            }
        } else if (l == 0) {
            const int m = k + 1;
            if (m < NB && lane20) {
                #pragma unroll
                for (int i = 0; i < KSTEP; ++i) {
                    float4 v = __ldg(&gp4[((size_t)m * KSTEP + i) * H_DIM + jj]);
                    *(float4*)&pre[p ^ 1][0][i][jj][0] = v;
                }
            }
        } else {
            const int m = k + 1 - 2 * l;
            if (m >= 0 && m < NB) {
                #pragma unroll
                for (int i = 0; i < KSTEP; ++i) {
                    const ulonglong2* vp =
                        (const ulonglong2*)&hx[p ^ 1][l - 1][i][0];
                    ulonglong2 v0 = vp[0], v1 = vp[1], v2 = vp[2],
                               v3 = vp[3], v4 = vp[4];
                    unsigned long long a0x = pack1(bias4[0]), a0y = 0ull;
                    unsigned long long a1x = pack1(bias4[1]), a1y = 0ull;
                    unsigned long long a2x = pack1(bias4[2]), a2y = 0ull;
                    unsigned long long a3x = pack1(bias4[3]), a3y = 0ull;
                    #pragma unroll
                    for (int q = 0; q < 5; ++q) {
                        ulonglong2 vv = (q == 0) ? v0 : (q == 1) ? v1 :
                                        (q == 2) ? v2 : (q == 3) ? v3 : v4;
                        a0x = fma2(wv[0][2*q], vv.x, a0x);
                        a0y = fma2(wv[0][2*q+1], vv.y, a0y);
                        a1x = fma2(wv[1][2*q], vv.x, a1x);
                        a1y = fma2(wv[1][2*q+1], vv.y, a1y);
                        a2x = fma2(wv[2][2*q], vv.x, a2x);
                        a2y = fma2(wv[2][2*q+1], vv.y, a2y);
                        a3x = fma2(wv[3][2*q], vv.x, a3x);
                        a3y = fma2(wv[3][2*q+1], vv.y, a3y);
                    }
                    unsigned long long s0 = add2(a0x, a0y);
                    unsigned long long s1 = add2(a1x, a1y);
                    unsigned long long s2 = add2(a2x, a2y);
                    unsigned long long s3 = add2(a3x, a3y);
                    if (lane20) {
                        float4 pr;
                        pr.x = lo32(s0) + hi32(s0);
                        pr.y = lo32(s1) + hi32(s1);
                        pr.z = lo32(s2) + hi32(s2);
                        pr.w = lo32(s3) + hi32(s3);
                        *(float4*)&pre[p ^ 1][l][i][jj][0] = pr;
                    }
                }
            }
        }

        __syncthreads();   // orders pre/hx handoff between phases
    }
}

// ---------------------------------------------------------------------------
extern "C" void kernel_launch(void* const* d_in, const int* in_sizes, int n_in,
                              void* d_out, int out_size)
{
    const float* x      = (const float*)d_in[0];
    const float* W_ih0  = (const float*)d_in[1];
    const float* W_hh0  = (const float*)d_in[2];
    const float* b_ih0  = (const float*)d_in[3];
    const float* b_hh0  = (const float*)d_in[4];
    const float* W_ih_r = (const float*)d_in[5];
    const float* W_hh_r = (const float*)d_in[6];
    const float* b_ih_r = (const float*)d_in[7];
    const float* b_hh_r = (const float*)d_in[8];
    const float* lin_w  = (const float*)d_in[9];
    const float* lin_b  = (const float*)d_in[10];

    proj_kernel<<<T_SEQ / 8, 160>>>(x, W_ih0, b_ih0, b_hh0);
    rnn_kernel<<<1, 256>>>(W_hh0, W_ih_r, W_hh_r, b_ih_r, b_hh_r,
                           lin_w, lin_b, (float*)d_out);
}

// round 11
// speedup vs baseline: 2.5644x; 1.0455x over previous
#include <cuda_runtime.h>
#include <cuda_bf16.h>
#include <stdint.h>

#define T_SEQ   32768
#define IN_DIM  1024
#define H_DIM   20
#define NLAYER  4
#define G4      80
#define KSTEP   8
#define NB      (T_SEQ / KSTEP)
#define NPHASE  (NB + 6)

// Layer-0 input projection, layout [t][unit][gate] (both biases folded). 10.5 MB
__device__ float g_proj[T_SEQ * G4];

// ---------------------------------------------------------------------------
// Kernel 1: proj = x @ W_ih0^T + b_ih0 + b_hh0, stored [t][unit*4 + gate]
// ---------------------------------------------------------------------------
__global__ __launch_bounds__(160) void proj_kernel(
    const float* __restrict__ x,
    const float* __restrict__ W,
    const float* __restrict__ bi,
    const float* __restrict__ bh)
{
    __shared__ __align__(16) float xs[8 * IN_DIM];
    const int t0 = blockIdx.x * 8;

    const float4* xg  = (const float4*)(x + (size_t)t0 * IN_DIM);
    float4*       xs4 = (float4*)xs;
    for (int i = threadIdx.x; i < 8 * (IN_DIM / 4); i += blockDim.x)
        xs4[i] = xg[i];
    __syncthreads();

    const int tid = threadIdx.x;
    if (tid >= 160) return;
    const int g  = tid % 80;            // weight row: gate = g/20, unit = g%20
    const int th = tid / 80;
    const int didx = (g % 20) * 4 + (g / 20);   // dest offset within row

    const float4* Wg = (const float4*)(W + (size_t)g * IN_DIM);
    float a0 = 0.f, a1 = 0.f, a2 = 0.f, a3 = 0.f;

    #pragma unroll 4
    for (int kk = 0; kk < IN_DIM / 4; ++kk) {
        float4 w4 = Wg[kk];
        float4 v0 = xs4[(th * 4 + 0) * (IN_DIM / 4) + kk];
        float4 v1 = xs4[(th * 4 + 1) * (IN_DIM / 4) + kk];
        float4 v2 = xs4[(th * 4 + 2) * (IN_DIM / 4) + kk];
        float4 v3 = xs4[(th * 4 + 3) * (IN_DIM / 4) + kk];
        a0 = fmaf(w4.x, v0.x, a0); a0 = fmaf(w4.y, v0.y, a0);
        a0 = fmaf(w4.z, v0.z, a0); a0 = fmaf(w4.w, v0.w, a0);
        a1 = fmaf(w4.x, v1.x, a1); a1 = fmaf(w4.y, v1.y, a1);
        a1 = fmaf(w4.z, v1.z, a1); a1 = fmaf(w4.w, v1.w, a1);
        a2 = fmaf(w4.x, v2.x, a2); a2 = fmaf(w4.y, v2.y, a2);
        a2 = fmaf(w4.z, v2.z, a2); a2 = fmaf(w4.w, v2.w, a2);
        a3 = fmaf(w4.x, v3.x, a3); a3 = fmaf(w4.y, v3.y, a3);
        a3 = fmaf(w4.z, v3.z, a3); a3 = fmaf(w4.w, v3.w, a3);
    }

    const float b = bi[g] + bh[g];
    const int tb = t0 + th * 4;
    g_proj[(size_t)(tb + 0) * G4 + didx] = a0 + b;
    g_proj[(size_t)(tb + 1) * G4 + didx] = a1 + b;
    g_proj[(size_t)(tb + 2) * G4 + didx] = a2 + b;
    g_proj[(size_t)(tb + 3) * G4 + didx] = a3 + b;
}

// ---------------------------------------------------------------------------
__device__ __forceinline__ unsigned long long fma2(
    unsigned long long a, unsigned long long b, unsigned long long c)
{
    unsigned long long d;
    asm("fma.rn.f32x2 %0, %1, %2, %3;" : "=l"(d) : "l"(a), "l"(b), "l"(c));
    return d;
}
__device__ __forceinline__ unsigned long long add2(
    unsigned long long a, unsigned long long b)
{
    unsigned long long d;
    asm("add.rn.f32x2 %0, %1, %2;" : "=l"(d) : "l"(a), "l"(b));
    return d;
}
__device__ __forceinline__ float lo32(unsigned long long u) {
    return __uint_as_float((unsigned)u);
}
__device__ __forceinline__ float hi32(unsigned long long u) {
    return __uint_as_float((unsigned)(u >> 32));
}
__device__ __forceinline__ unsigned long long pack1(float lo) {
    return (unsigned long long)__float_as_uint(lo);   // (lo, 0.0f)
}
__device__ __forceinline__ float tanh_fast(float x) {
    float y;
    asm("tanh.approx.f32 %0, %1;" : "=f"(y) : "f"(x));
    return y;
}
__device__ __forceinline__ float sig_fast(float x) {
    return fmaf(tanh_fast(0.5f * x), 0.5f, 0.5f);
}

// ---------------------------------------------------------------------------
// Kernel 2: block-pipelined, idle lanes repurposed. 256 threads = 8 warps.
//  mains wid 0..3 (layer l): at phase k process block b = k-2l.
//    lanes 0..19 : unit j's 4 gates, own-h dot (rides the 40-fma2 stream)
//    lanes 20..31: unit (j-20)'s 4 gates, INPUT dot for block b+1 (same
//                  stream, different weights + LDS base) -> pre[p^1]
//  helpers wid 4..7 (l>0): units 12..19 input dots, 1 gate-dot per lane
//    (10-fma2 chain); helper 0 stages g_proj for layer 0.
// ONE __syncthreads per phase orders all pre/hx handoff (parity buffers).
// ---------------------------------------------------------------------------
__global__ __launch_bounds__(256, 1) void rnn_kernel(
    const float* __restrict__ W_hh0,   // [80][20]
    const float* __restrict__ W_ih_r,  // [3][80][20]
    const float* __restrict__ W_hh_r,  // [3][80][20]
    const float* __restrict__ b_ih_r,  // [3][80]
    const float* __restrict__ b_hh_r,  // [3][80]
    const float* __restrict__ lin_w,   // [20]
    const float* __restrict__ lin_b,   // [1]
    float* __restrict__ out)
{
    const int tid = threadIdx.x;
    const int wid = tid >> 5;
    const int j   = tid & 31;
    const int jj  = (j < H_DIM) ? j : H_DIM - 1;
    const bool lane20 = (j < H_DIM);

    __shared__ __align__(16) float pre[2][NLAYER][KSTEP][H_DIM][4];
    __shared__ __align__(16) float hx [2][NLAYER][KSTEP][24];
    __shared__ __align__(16) float hb [NLAYER][24];

    for (int i = tid; i < NLAYER * 24; i += blockDim.x)
        ((float*)hb)[i] = 0.f;
    for (int i = tid; i < 2 * NLAYER * KSTEP * 24; i += blockDim.x)
        ((float*)hx)[i] = 0.f;

    const bool is_main = (wid < NLAYER);
    const int  l       = wid & 3;
    const int  lm1     = (l > 0) ? (l - 1) : 0;

    // ---- weights ----
    unsigned long long wv[4][10];
    unsigned long long wh[10];
    float bias4[4] = {0.f, 0.f, 0.f, 0.f};
    float biash = 0.f;
    #pragma unroll
    for (int g = 0; g < 4; ++g)
        #pragma unroll
        for (int kk = 0; kk < 10; ++kk) wv[g][kk] = 0ull;
    #pragma unroll
    for (int kk = 0; kk < 10; ++kk) wh[kk] = 0ull;

    if (is_main) {
        if (lane20) {
            // own-h (recurrent) rows for unit j
            #pragma unroll
            for (int g = 0; g < 4; ++g) {
                const int row = g * H_DIM + j;
                const float* Ws = (l == 0) ? (W_hh0 + row * H_DIM)
                                           : (W_hh_r + (l - 1) * 1600 + row * H_DIM);
                #pragma unroll
                for (int kk = 0; kk < 10; ++kk)
                    wv[g][kk] = (unsigned long long)__float_as_uint(Ws[2 * kk]) |
                                ((unsigned long long)__float_as_uint(Ws[2 * kk + 1]) << 32);
            }
        } else if (l > 0) {
            // input rows for unit u = j-20 (0..11)
            const int u = j - H_DIM;
            #pragma unroll
            for (int g = 0; g < 4; ++g) {
                const int row = g * H_DIM + u;
                const float* Ws = W_ih_r + (l - 1) * 1600 + row * H_DIM;
                #pragma unroll
                for (int kk = 0; kk < 10; ++kk)
                    wv[g][kk] = (unsigned long long)__float_as_uint(Ws[2 * kk]) |
                                ((unsigned long long)__float_as_uint(Ws[2 * kk + 1]) << 32);
                bias4[g] = b_ih_r[(l - 1) * G4 + row] + b_hh_r[(l - 1) * G4 + row];
            }
        }
    } else if (l > 0) {
        // helper: unit u = 12 + (j>>2), gate gg = j&3
        const int u  = 12 + (j >> 2);
        const int gg = j & 3;
        const int row = gg * H_DIM + u;
        const float* Ws = W_ih_r + (l - 1) * 1600 + row * H_DIM;
        #pragma unroll
        for (int kk = 0; kk < 10; ++kk)
            wh[kk] = (unsigned long long)__float_as_uint(Ws[2 * kk]) |
                     ((unsigned long long)__float_as_uint(Ws[2 * kk + 1]) << 32);
        biash = b_ih_r[(l - 1) * G4 + row] + b_hh_r[(l - 1) * G4 + row];
    }
    const float lw = lane20 ? lin_w[jj] : 0.f;
    const float lb = lin_b[0];

    const float4* gp4 = (const float4*)g_proj;   // [t][20 float4]

    // prologue: helper 0 stages block 0
    if (!is_main && l == 0 && lane20) {
        #pragma unroll
        for (int i = 0; i < KSTEP; ++i) {
            float4 v = __ldg(&gp4[(size_t)i * H_DIM + jj]);
            *(float4*)&pre[0][0][i][jj][0] = v;
        }
    }
    float c = 0.f;
    float hlast = 0.f;
    __syncthreads();

    const unsigned FULL = 0xffffffffu;

    for (int k = 0; k < NPHASE; ++k) {
        const int p = k & 1;

        if (is_main) {
            const int b  = k - 2 * l;           // lanes 0..19: this block
            const int mv = k + 1 - 2 * l;       // lanes 20..31: pre for this block
            const bool bval = (b >= 0) && (b < NB);
            const bool mval = (mv >= 0) && (mv < NB) && (l > 0);
            if (bval || mval) {
                for (int i = 0; i < KSTEP; ++i) {
                    __syncwarp();
                    const float4 pr = *(const float4*)&pre[p][l][i][jj][0];
                    unsigned long long ax[4], ay[4];
                    ax[0] = pack1(lane20 ? pr.x : bias4[0]);
                    ax[1] = pack1(lane20 ? pr.y : bias4[1]);
                    ax[2] = pack1(lane20 ? pr.z : bias4[2]);
                    ax[3] = pack1(lane20 ? pr.w : bias4[3]);
                    ay[0] = ay[1] = ay[2] = ay[3] = 0ull;
                    const ulonglong2* vp = lane20
                        ? (const ulonglong2*)&hb[l][0]
                        : (const ulonglong2*)&hx[p ^ 1][lm1][i][0];
                    #pragma unroll
                    for (int q = 0; q < 5; ++q) {
                        const ulonglong2 vv = vp[q];
                        #pragma unroll
                        for (int g = 0; g < 4; ++g) {
                            ax[g] = fma2(wv[g][2 * q],     vv.x, ax[g]);
                            ay[g] = fma2(wv[g][2 * q + 1], vv.y, ay[g]);
                        }
                    }
                    float gv[4];
                    #pragma unroll
                    for (int g = 0; g < 4; ++g) {
                        const unsigned long long s = add2(ax[g], ay[g]);
                        gv[g] = lo32(s) + hi32(s);
                    }
                    if (lane20) {
                        if (bval) {
                            float fi = sig_fast(gv[0]);
                            float ff = sig_fast(gv[1]);
                            float fg = tanh_fast(gv[2]);
                            float fo = sig_fast(gv[3]);
                            c = fmaf(ff, c, fi * fg);
                            float h = fo * tanh_fast(c);
                            hlast = h;
                            hb[l][j] = h;
                            if (l < 3) hx[p][l][i][j] = h;
                        }
                    } else if (mval) {
                        float4 o;
                        o.x = gv[0]; o.y = gv[1]; o.z = gv[2]; o.w = gv[3];
                        *(float4*)&pre[p ^ 1][l][i][j - H_DIM][0] = o;
                    }
                }
                if (l == 3 && b == NB - 1) {
                    float part = hlast * lw;   // lw = 0 for lanes >= 20
                    #pragma unroll
                    for (int off = 16; off; off >>= 1)
                        part += __shfl_xor_sync(FULL, part, off);
                    if (j == 0) out[0] = sig_fast(part + lb);
                }
            }
        } else if (l == 0) {
            // helper 0: stage g_proj for block k+1
            const int m = k + 1;
            if (m < NB && lane20) {
                for (int i = 0; i < KSTEP; ++i) {
                    float4 v = __ldg(&gp4[((size_t)m * KSTEP + i) * H_DIM + jj]);
                    *(float4*)&pre[p ^ 1][0][i][jj][0] = v;
                }
            }
        } else {
            // helper l>0: units 12..19, one gate-dot per lane
            const int m = k + 1 - 2 * l;
            if (m >= 0 && m < NB) {
                const int u  = 12 + (j >> 2);
                const int gg = j & 3;
                for (int i = 0; i < KSTEP; ++i) {
                    const unsigned long long* vp =
                        (const unsigned long long*)&hx[p ^ 1][l - 1][i][0];
                    unsigned long long acc = pack1(biash);
                    #pragma unroll
                    for (int q = 0; q < 10; ++q)
                        acc = fma2(wh[q], vp[q], acc);
                    pre[p ^ 1][l][i][u][gg] = lo32(acc) + hi32(acc);
                }
            }
        }

        __syncthreads();   // orders pre/hx handoff between phases
    }
}

// ---------------------------------------------------------------------------
extern "C" void kernel_launch(void* const* d_in, const int* in_sizes, int n_in,
                              void* d_out, int out_size)
{
    const float* x      = (const float*)d_in[0];
    const float* W_ih0  = (const float*)d_in[1];
    const float* W_hh0  = (const float*)d_in[2];
    const float* b_ih0  = (const float*)d_in[3];
    const float* b_hh0  = (const float*)d_in[4];
    const float* W_ih_r = (const float*)d_in[5];
    const float* W_hh_r = (const float*)d_in[6];
    const float* b_ih_r = (const float*)d_in[7];
    const float* b_hh_r = (const float*)d_in[8];
    const float* lin_w  = (const float*)d_in[9];
    const float* lin_b  = (const float*)d_in[10];

    proj_kernel<<<T_SEQ / 8, 160>>>(x, W_ih0, b_ih0, b_hh0);
    rnn_kernel<<<1, 256>>>(W_hh0, W_ih_r, W_hh_r, b_ih_r, b_hh_r,
                           lin_w, lin_b, (float*)d_out);
}

// round 14
// speedup vs baseline: 3.0556x; 1.1915x over previous
#include <cuda_runtime.h>
#include <cuda_bf16.h>
#include <stdint.h>

#define T_SEQ   32768
#define IN_DIM  1024
#define H_DIM   20
#define NLAYER  4
#define G4      80
#define KSTEP   8
#define NB      (T_SEQ / KSTEP)
#define NPHASE  (NB + 2 * (NLAYER - 1))

// Layer-0 input projection, layout [t][unit][gate], sigmoid rows pre-scaled
// by 0.5 (both biases folded). 10.5 MB
__device__ float g_proj[T_SEQ * G4];

// ---------------------------------------------------------------------------
// Kernel 1: proj = (x @ W_ih0^T + b_ih0 + b_hh0) * sc(gate), [t][unit*4+gate]
// sc = 0.5 for sigmoid gates (i,f,o), 1.0 for tanh gate (g).
// ---------------------------------------------------------------------------
__global__ __launch_bounds__(160) void proj_kernel(
    const float* __restrict__ x,
    const float* __restrict__ W,
    const float* __restrict__ bi,
    const float* __restrict__ bh)
{
    __shared__ __align__(16) float xs[8 * IN_DIM];
    const int t0 = blockIdx.x * 8;

    const float4* xg  = (const float4*)(x + (size_t)t0 * IN_DIM);
    float4*       xs4 = (float4*)xs;
    for (int i = threadIdx.x; i < 8 * (IN_DIM / 4); i += blockDim.x)
        xs4[i] = xg[i];
    __syncthreads();

    const int tid = threadIdx.x;
    if (tid >= 160) return;
    const int g  = tid % 80;            // weight row: gate = g/20, unit = g%20
    const int th = tid / 80;
    const int didx = (g % 20) * 4 + (g / 20);
    const float sc = ((g / 20) == 2) ? 1.0f : 0.5f;

    const float4* Wg = (const float4*)(W + (size_t)g * IN_DIM);
    float a0 = 0.f, a1 = 0.f, a2 = 0.f, a3 = 0.f;

    #pragma unroll 4
    for (int kk = 0; kk < IN_DIM / 4; ++kk) {
        float4 w4 = Wg[kk];
        float4 v0 = xs4[(th * 4 + 0) * (IN_DIM / 4) + kk];
        float4 v1 = xs4[(th * 4 + 1) * (IN_DIM / 4) + kk];
        float4 v2 = xs4[(th * 4 + 2) * (IN_DIM / 4) + kk];
        float4 v3 = xs4[(th * 4 + 3) * (IN_DIM / 4) + kk];
        a0 = fmaf(w4.x, v0.x, a0); a0 = fmaf(w4.y, v0.y, a0);
        a0 = fmaf(w4.z, v0.z, a0); a0 = fmaf(w4.w, v0.w, a0);
        a1 = fmaf(w4.x, v1.x, a1); a1 = fmaf(w4.y, v1.y, a1);
        a1 = fmaf(w4.z, v1.z, a1); a1 = fmaf(w4.w, v1.w, a1);
        a2 = fmaf(w4.x, v2.x, a2); a2 = fmaf(w4.y, v2.y, a2);
        a2 = fmaf(w4.z, v2.z, a2); a2 = fmaf(w4.w, v2.w, a2);
        a3 = fmaf(w4.x, v3.x, a3); a3 = fmaf(w4.y, v3.y, a3);
        a3 = fmaf(w4.z, v3.z, a3); a3 = fmaf(w4.w, v3.w, a3);
    }

    const float b = bi[g] + bh[g];
    const int tb = t0 + th * 4;
    g_proj[(size_t)(tb + 0) * G4 + didx] = (a0 + b) * sc;
    g_proj[(size_t)(tb + 1) * G4 + didx] = (a1 + b) * sc;
    g_proj[(size_t)(tb + 2) * G4 + didx] = (a2 + b) * sc;
    g_proj[(size_t)(tb + 3) * G4 + didx] = (a3 + b) * sc;
}

// ---------------------------------------------------------------------------
__device__ __forceinline__ unsigned long long fma2(
    unsigned long long a, unsigned long long b, unsigned long long c)
{
    unsigned long long d;
    asm("fma.rn.f32x2 %0, %1, %2, %3;" : "=l"(d) : "l"(a), "l"(b), "l"(c));
    return d;
}
__device__ __forceinline__ unsigned long long add2(
    unsigned long long a, unsigned long long b)
{
    unsigned long long d;
    asm("add.rn.f32x2 %0, %1, %2;" : "=l"(d) : "l"(a), "l"(b));
    return d;
}
__device__ __forceinline__ float lo32(unsigned long long u) {
    return __uint_as_float((unsigned)u);
}
__device__ __forceinline__ float hi32(unsigned long long u) {
    return __uint_as_float((unsigned)(u >> 32));
}
__device__ __forceinline__ unsigned long long pack1(float lo) {
    return (unsigned long long)__float_as_uint(lo);   // (lo, 0.0f)
}
__device__ __forceinline__ float tanh_fast(float x) {
    float y;
    asm("tanh.approx.f32 %0, %1;" : "=f"(y) : "f"(x));
    return y;
}
__device__ __forceinline__ float sig_fast(float x) {
    return fmaf(tanh_fast(0.5f * x), 0.5f, 0.5f);
}
// predicated stores (no BSSY/BSYNC divergence penalty)
__device__ __forceinline__ void st_pred(bool pG, float* addr, float v) {
    asm volatile(
        "{ .reg .pred p; setp.ne.u32 p, %0, 0; @p st.f32 [%1], %2; }"
        :: "r"((int)pG), "l"(addr), "f"(v) : "memory");
}
__device__ __forceinline__ void st4_pred(bool pG, float* addr,
                                         float a, float b, float c, float d) {
    asm volatile(
        "{ .reg .pred p; setp.ne.u32 p, %0, 0; @p st.v4.f32 [%1], {%2,%3,%4,%5}; }"
        :: "r"((int)pG), "l"(addr), "f"(a), "f"(b), "f"(c), "f"(d) : "memory");
}

// ---------------------------------------------------------------------------
// Kernel 2: block-pipelined, branchless inner loop, no per-step syncwarp.
//  mains wid 0..3 (layer l): phase k -> block b = k-2l; lanes 0..19 own-h
//  recurrence, lanes 20..31 input dots for block b+1 (same fma2 stream).
//  helpers wid 4..7: units 12..19 input dots (l>0) / g_proj stager (l=0).
// Sigmoid-path weights pre-scaled by 0.5: sig = fma(tanh(acc),.5,.5).
// Intra-warp h handoff relies on per-warp in-order LSU processing of the
// single predicated (branch-free) instruction stream: STS hb precedes the
// next iteration's LDS hb in program order.
// ONE __syncthreads per phase orders all pre/hx handoff (parity buffers).
// ---------------------------------------------------------------------------
__global__ __launch_bounds__(256, 1) void rnn_kernel(
    const float* __restrict__ W_hh0,   // [80][20]
    const float* __restrict__ W_ih_r,  // [3][80][20]
    const float* __restrict__ W_hh_r,  // [3][80][20]
    const float* __restrict__ b_ih_r,  // [3][80]
    const float* __restrict__ b_hh_r,  // [3][80]
    const float* __restrict__ lin_w,   // [20]
    const float* __restrict__ lin_b,   // [1]
    float* __restrict__ out)
{
    const int tid = threadIdx.x;
    const int wid = tid >> 5;
    const int j   = tid & 31;
    const int jj  = (j < H_DIM) ? j : H_DIM - 1;
    const bool lane20 = (j < H_DIM);
    const int ujj = lane20 ? 0 : (j - H_DIM);   // store unit for lanes >= 20

    __shared__ __align__(16) float pre[2][NLAYER][KSTEP][H_DIM][4];
    __shared__ __align__(16) float hx [2][NLAYER][KSTEP][24];
    __shared__ __align__(16) float hb [NLAYER][24];

    for (int i = tid; i < NLAYER * 24; i += blockDim.x)
        ((float*)hb)[i] = 0.f;
    for (int i = tid; i < 2 * NLAYER * KSTEP * 24; i += blockDim.x)
        ((float*)hx)[i] = 0.f;

    const bool is_main = (wid < NLAYER);
    const int  l       = wid & 3;
    const int  lm1     = (l > 0) ? (l - 1) : 0;

    // ---- weights (sigmoid rows pre-scaled by 0.5) ----
    unsigned long long wv[4][10];
    unsigned long long wh[10];
    float bias4[4] = {0.f, 0.f, 0.f, 0.f};
    float biash = 0.f;
    #pragma unroll
    for (int g = 0; g < 4; ++g)
        #pragma unroll
        for (int kk = 0; kk < 10; ++kk) wv[g][kk] = 0ull;
    #pragma unroll
    for (int kk = 0; kk < 10; ++kk) wh[kk] = 0ull;

    if (is_main) {
        if (lane20) {
            #pragma unroll
            for (int g = 0; g < 4; ++g) {
                const float sc = (g == 2) ? 1.0f : 0.5f;
                const int row = g * H_DIM + j;
                const float* Ws = (l == 0) ? (W_hh0 + row * H_DIM)
                                           : (W_hh_r + (l - 1) * 1600 + row * H_DIM);
                #pragma unroll
                for (int kk = 0; kk < 10; ++kk)
                    wv[g][kk] = (unsigned long long)__float_as_uint(Ws[2 * kk] * sc) |
                                ((unsigned long long)__float_as_uint(Ws[2 * kk + 1] * sc) << 32);
            }
        } else if (l > 0) {
            const int u = j - H_DIM;
            #pragma unroll
            for (int g = 0; g < 4; ++g) {
                const float sc = (g == 2) ? 1.0f : 0.5f;
                const int row = g * H_DIM + u;
                const float* Ws = W_ih_r + (l - 1) * 1600 + row * H_DIM;
                #pragma unroll
                for (int kk = 0; kk < 10; ++kk)
                    wv[g][kk] = (unsigned long long)__float_as_uint(Ws[2 * kk] * sc) |
                                ((unsigned long long)__float_as_uint(Ws[2 * kk + 1] * sc) << 32);
                bias4[g] = (b_ih_r[(l - 1) * G4 + row] + b_hh_r[(l - 1) * G4 + row]) * sc;
            }
        }
    } else if (l > 0) {
        const int u  = 12 + (j >> 2);
        const int gg = j & 3;
        const float sc = (gg == 2) ? 1.0f : 0.5f;
        const int row = gg * H_DIM + u;
        const float* Ws = W_ih_r + (l - 1) * 1600 + row * H_DIM;
        #pragma unroll
        for (int kk = 0; kk < 10; ++kk)
            wh[kk] = (unsigned long long)__float_as_uint(Ws[2 * kk] * sc) |
                     ((unsigned long long)__float_as_uint(Ws[2 * kk + 1] * sc) << 32);
        biash = (b_ih_r[(l - 1) * G4 + row] + b_hh_r[(l - 1) * G4 + row]) * sc;
    }
    const float lw = lane20 ? lin_w[jj] : 0.f;
    const float lb = lin_b[0];

    const float4* gp4 = (const float4*)g_proj;   // [t][20 float4]

    // prologue: helper 0 stages block 0
    if (!is_main && l == 0 && lane20) {
        #pragma unroll
        for (int i = 0; i < KSTEP; ++i) {
            float4 v = __ldg(&gp4[(size_t)i * H_DIM + jj]);
            *(float4*)&pre[0][0][i][jj][0] = v;
        }
    }
    float c = 0.f;
    float hlast = 0.f;
    __syncthreads();

    const unsigned FULL = 0xffffffffu;

    for (int k = 0; k < NPHASE; ++k) {
        const int p = k & 1;

        if (is_main) {
            const int b  = k - 2 * l;
            const int mv = k + 1 - 2 * l;
            const bool bval = (b >= 0) && (b < NB);
            const bool mval = (mv >= 0) && (mv < NB) && (l > 0);
            if (bval || mval) {
                for (int i = 0; i < KSTEP; ++i) {
                    const float4 pr = *(const float4*)&pre[p][l][i][jj][0];
                    unsigned long long ax[4], ay[4];
                    ax[0] = pack1(lane20 ? pr.x : bias4[0]);
                    ax[1] = pack1(lane20 ? pr.y : bias4[1]);
                    ax[2] = pack1(lane20 ? pr.z : bias4[2]);
                    ax[3] = pack1(lane20 ? pr.w : bias4[3]);
                    ay[0] = ay[1] = ay[2] = ay[3] = 0ull;
                    const ulonglong2* vp = lane20
                        ? (const ulonglong2*)&hb[l][0]
                        : (const ulonglong2*)&hx[p ^ 1][lm1][i][0];
                    #pragma unroll
                    for (int q = 0; q < 5; ++q) {
                        const ulonglong2 vv = vp[q];
                        #pragma unroll
                        for (int g = 0; g < 4; ++g) {
                            ax[g] = fma2(wv[g][2 * q],     vv.x, ax[g]);
                            ay[g] = fma2(wv[g][2 * q + 1], vv.y, ay[g]);
                        }
                    }
                    float gv[4];
                    #pragma unroll
                    for (int g = 0; g < 4; ++g) {
                        const unsigned long long s = add2(ax[g], ay[g]);
                        gv[g] = lo32(s) + hi32(s);
                    }
                    // activations (sig inputs pre-scaled by 0.5)
                    const float fi = fmaf(tanh_fast(gv[0]), 0.5f, 0.5f);
                    const float ff = fmaf(tanh_fast(gv[1]), 0.5f, 0.5f);
                    const float fg = tanh_fast(gv[2]);
                    const float fo = fmaf(tanh_fast(gv[3]), 0.5f, 0.5f);
                    const float nc = fmaf(ff, c, fi * fg);
                    const float nh = fo * tanh_fast(nc);

                    const bool upd = lane20 & bval;
                    c     = upd ? nc : c;
                    hlast = upd ? nh : hlast;
                    st_pred(upd, &hb[l][j], nh);
                    st_pred(upd & (l < 3), &hx[p][l][i][j], nh);
                    st4_pred((!lane20) & mval, &pre[p ^ 1][l][i][ujj][0],
                             gv[0], gv[1], gv[2], gv[3]);
                }
                if (l == 3 && b == NB - 1) {
                    float part = hlast * lw;   // lw = 0 for lanes >= 20
                    #pragma unroll
                    for (int off = 16; off; off >>= 1)
                        part += __shfl_xor_sync(FULL, part, off);
                    if (j == 0) out[0] = sig_fast(part + lb);
                }
            }
        } else if (l == 0) {
            const int m = k + 1;
            if (m < NB && lane20) {
                for (int i = 0; i < KSTEP; ++i) {
                    float4 v = __ldg(&gp4[((size_t)m * KSTEP + i) * H_DIM + jj]);
                    *(float4*)&pre[p ^ 1][0][i][jj][0] = v;
                }
            }
        } else {
            const int m = k + 1 - 2 * l;
            if (m >= 0 && m < NB) {
                const int u  = 12 + (j >> 2);
                const int gg = j & 3;
                for (int i = 0; i < KSTEP; ++i) {
                    const unsigned long long* vp =
                        (const unsigned long long*)&hx[p ^ 1][l - 1][i][0];
                    unsigned long long acc = pack1(biash);
                    #pragma unroll
                    for (int q = 0; q < 10; ++q)
                        acc = fma2(wh[q], vp[q], acc);
                    pre[p ^ 1][l][i][u][gg] = lo32(acc) + hi32(acc);
                }
            }
        }

        __syncthreads();   // orders pre/hx handoff between phases
    }
}

// ---------------------------------------------------------------------------
extern "C" void kernel_launch(void* const* d_in, const int* in_sizes, int n_in,
                              void* d_out, int out_size)
{
    const float* x      = (const float*)d_in[0];
    const float* W_ih0  = (const float*)d_in[1];
    const float* W_hh0  = (const float*)d_in[2];
    const float* b_ih0  = (const float*)d_in[3];
    const float* b_hh0  = (const float*)d_in[4];
    const float* W_ih_r = (const float*)d_in[5];
    const float* W_hh_r = (const float*)d_in[6];
    const float* b_ih_r = (const float*)d_in[7];
    const float* b_hh_r = (const float*)d_in[8];
    const float* lin_w  = (const float*)d_in[9];
    const float* lin_b  = (const float*)d_in[10];

    proj_kernel<<<T_SEQ / 8, 160>>>(x, W_ih0, b_ih0, b_hh0);
    rnn_kernel<<<1, 256>>>(W_hh0, W_ih_r, W_hh_r, b_ih_r, b_hh_r,
                           lin_w, lin_b, (float*)d_out);
}

// round 15
// speedup vs baseline: 3.1191x; 1.0208x over previous
#include <cuda_runtime.h>
#include <cuda_bf16.h>
#include <stdint.h>

#define T_SEQ   32768
#define IN_DIM  1024
#define H_DIM   20
#define NLAYER  4
#define G4      80
#define KSTEP   8
#define NB      (T_SEQ / KSTEP)
#define NPHASE  (NB + 2 * (NLAYER - 1))

// Layer-0 input projection, layout [t][unit][gate], sigmoid rows pre-scaled
// by 0.5 (both biases folded). 10.5 MB
__device__ float g_proj[T_SEQ * G4];

// ---------------------------------------------------------------------------
// Kernel 1: proj = (x @ W_ih0^T + b_ih0 + b_hh0) * sc(gate), [t][unit*4+gate]
// sc = 0.5 for sigmoid gates (i,f,o), 1.0 for tanh gate (g).
// ---------------------------------------------------------------------------
__global__ __launch_bounds__(160) void proj_kernel(
    const float* __restrict__ x,
    const float* __restrict__ W,
    const float* __restrict__ bi,
    const float* __restrict__ bh)
{
    __shared__ __align__(16) float xs[8 * IN_DIM];
    const int t0 = blockIdx.x * 8;

    const float4* xg  = (const float4*)(x + (size_t)t0 * IN_DIM);
    float4*       xs4 = (float4*)xs;
    for (int i = threadIdx.x; i < 8 * (IN_DIM / 4); i += blockDim.x)
        xs4[i] = xg[i];
    __syncthreads();

    const int tid = threadIdx.x;
    if (tid >= 160) return;
    const int g  = tid % 80;            // weight row: gate = g/20, unit = g%20
    const int th = tid / 80;
    const int didx = (g % 20) * 4 + (g / 20);
    const float sc = ((g / 20) == 2) ? 1.0f : 0.5f;

    const float4* Wg = (const float4*)(W + (size_t)g * IN_DIM);
    float a0 = 0.f, a1 = 0.f, a2 = 0.f, a3 = 0.f;

    #pragma unroll 4
    for (int kk = 0; kk < IN_DIM / 4; ++kk) {
        float4 w4 = Wg[kk];
        float4 v0 = xs4[(th * 4 + 0) * (IN_DIM / 4) + kk];
        float4 v1 = xs4[(th * 4 + 1) * (IN_DIM / 4) + kk];
        float4 v2 = xs4[(th * 4 + 2) * (IN_DIM / 4) + kk];
        float4 v3 = xs4[(th * 4 + 3) * (IN_DIM / 4) + kk];
        a0 = fmaf(w4.x, v0.x, a0); a0 = fmaf(w4.y, v0.y, a0);
        a0 = fmaf(w4.z, v0.z, a0); a0 = fmaf(w4.w, v0.w, a0);
        a1 = fmaf(w4.x, v1.x, a1); a1 = fmaf(w4.y, v1.y, a1);
        a1 = fmaf(w4.z, v1.z, a1); a1 = fmaf(w4.w, v1.w, a1);
        a2 = fmaf(w4.x, v2.x, a2); a2 = fmaf(w4.y, v2.y, a2);
        a2 = fmaf(w4.z, v2.z, a2); a2 = fmaf(w4.w, v2.w, a2);
        a3 = fmaf(w4.x, v3.x, a3); a3 = fmaf(w4.y, v3.y, a3);
        a3 = fmaf(w4.z, v3.z, a3); a3 = fmaf(w4.w, v3.w, a3);
    }

    const float b = bi[g] + bh[g];
    const int tb = t0 + th * 4;
    g_proj[(size_t)(tb + 0) * G4 + didx] = (a0 + b) * sc;
    g_proj[(size_t)(tb + 1) * G4 + didx] = (a1 + b) * sc;
    g_proj[(size_t)(tb + 2) * G4 + didx] = (a2 + b) * sc;
    g_proj[(size_t)(tb + 3) * G4 + didx] = (a3 + b) * sc;
}

// ---------------------------------------------------------------------------
__device__ __forceinline__ unsigned long long fma2(
    unsigned long long a, unsigned long long b, unsigned long long c)
{
    unsigned long long d;
    asm("fma.rn.f32x2 %0, %1, %2, %3;" : "=l"(d) : "l"(a), "l"(b), "l"(c));
    return d;
}
__device__ __forceinline__ unsigned long long add2(
    unsigned long long a, unsigned long long b)
{
    unsigned long long d;
    asm("add.rn.f32x2 %0, %1, %2;" : "=l"(d) : "l"(a), "l"(b));
    return d;
}
__device__ __forceinline__ float lo32(unsigned long long u) {
    return __uint_as_float((unsigned)u);
}
__device__ __forceinline__ float hi32(unsigned long long u) {
    return __uint_as_float((unsigned)(u >> 32));
}
__device__ __forceinline__ unsigned long long pack1(float lo) {
    return (unsigned long long)__float_as_uint(lo);   // (lo, 0.0f)
}
__device__ __forceinline__ float tanh_fast(float x) {
    float y;
    asm("tanh.approx.f32 %0, %1;" : "=f"(y) : "f"(x));
    return y;
}
__device__ __forceinline__ float sig_fast(float x) {
    return fmaf(tanh_fast(0.5f * x), 0.5f, 0.5f);
}
// predicated stores (no BSSY/BSYNC divergence penalty)
__device__ __forceinline__ void st_pred(bool pG, float* addr, float v) {
    asm volatile(
        "{ .reg .pred p; setp.ne.u32 p, %0, 0; @p st.f32 [%1], %2; }"
        :: "r"((int)pG), "l"(addr), "f"(v) : "memory");
}
__device__ __forceinline__ void st4_pred(bool pG, float* addr,
                                         float a, float b, float c, float d) {
    asm volatile(
        "{ .reg .pred p; setp.ne.u32 p, %0, 0; @p st.v4.f32 [%1], {%2,%3,%4,%5}; }"
        :: "r"((int)pG), "l"(addr), "f"(a), "f"(b), "f"(c), "f"(d) : "memory");
}

// ---------------------------------------------------------------------------
// Kernel 2: block-pipelined, branchless inner loop.
//  MAINS are wid 4..7 (HIGHEST arbiter priority: hi-wid-first RR), layer
//  l = wid-4; phase k -> block b = k-2l. lanes 0..19 own-h recurrence;
//  lanes 20..31 input dots for block b+1 (same fma2 stream).
//  HELPERS wid 0..3: units 12..19 input dots (l>0) / g_proj stager (l=0).
//  pre has 32 unit-rows: rows 20..31 pre-filled with bias4 in the prologue,
//  so mains read pre[...][j] with NO per-step selects or lane clamp.
// Sigmoid-path weights pre-scaled by 0.5: sig = fma(tanh(acc),.5,.5).
// ONE __syncthreads per phase orders all pre/hx handoff (parity buffers).
// ---------------------------------------------------------------------------
__global__ __launch_bounds__(256, 1) void rnn_kernel(
    const float* __restrict__ W_hh0,   // [80][20]
    const float* __restrict__ W_ih_r,  // [3][80][20]
    const float* __restrict__ W_hh_r,  // [3][80][20]
    const float* __restrict__ b_ih_r,  // [3][80]
    const float* __restrict__ b_hh_r,  // [3][80]
    const float* __restrict__ lin_w,   // [20]
    const float* __restrict__ lin_b,   // [1]
    float* __restrict__ out)
{
    const int tid = threadIdx.x;
    const int wid = tid >> 5;
    const int j   = tid & 31;
    const int jj  = (j < H_DIM) ? j : H_DIM - 1;
    const bool lane20 = (j < H_DIM);
    const int ujj = lane20 ? 0 : (j - H_DIM);   // store unit for lanes >= 20

    // pre: 32 unit-rows; rows 20..31 are constant bias rows after prologue.
    __shared__ __align__(16) float pre[2][NLAYER][KSTEP][32][4];   // 32 KB
    __shared__ __align__(16) float hx [2][NLAYER][KSTEP][24];      // 6 KB
    __shared__ __align__(16) float hb [NLAYER][24];

    for (int i = tid; i < NLAYER * 24; i += blockDim.x)
        ((float*)hb)[i] = 0.f;
    for (int i = tid; i < 2 * NLAYER * KSTEP * 24; i += blockDim.x)
        ((float*)hx)[i] = 0.f;

    const bool is_main = (wid >= NLAYER);   // mains on high wids
    const int  l       = wid & 3;
    const int  lm1     = (l > 0) ? (l - 1) : 0;

    // ---- weights (sigmoid rows pre-scaled by 0.5) ----
    unsigned long long wv[4][10];
    unsigned long long wh[10];
    float bias4[4] = {0.f, 0.f, 0.f, 0.f};
    float biash = 0.f;
    #pragma unroll
    for (int g = 0; g < 4; ++g)
        #pragma unroll
        for (int kk = 0; kk < 10; ++kk) wv[g][kk] = 0ull;
    #pragma unroll
    for (int kk = 0; kk < 10; ++kk) wh[kk] = 0ull;

    if (is_main) {
        if (lane20) {
            #pragma unroll
            for (int g = 0; g < 4; ++g) {
                const float sc = (g == 2) ? 1.0f : 0.5f;
                const int row = g * H_DIM + j;
                const float* Ws = (l == 0) ? (W_hh0 + row * H_DIM)
                                           : (W_hh_r + (l - 1) * 1600 + row * H_DIM);
                #pragma unroll
                for (int kk = 0; kk < 10; ++kk)
                    wv[g][kk] = (unsigned long long)__float_as_uint(Ws[2 * kk] * sc) |
                                ((unsigned long long)__float_as_uint(Ws[2 * kk + 1] * sc) << 32);
            }
        } else if (l > 0) {
            const int u = j - H_DIM;
            #pragma unroll
            for (int g = 0; g < 4; ++g) {
                const float sc = (g == 2) ? 1.0f : 0.5f;
                const int row = g * H_DIM + u;
                const float* Ws = W_ih_r + (l - 1) * 1600 + row * H_DIM;
                #pragma unroll
                for (int kk = 0; kk < 10; ++kk)
                    wv[g][kk] = (unsigned long long)__float_as_uint(Ws[2 * kk] * sc) |
                                ((unsigned long long)__float_as_uint(Ws[2 * kk + 1] * sc) << 32);
                bias4[g] = (b_ih_r[(l - 1) * G4 + row] + b_hh_r[(l - 1) * G4 + row]) * sc;
            }
        }
    } else if (l > 0) {
        const int u  = 12 + (j >> 2);
        const int gg = j & 3;
        const float sc = (gg == 2) ? 1.0f : 0.5f;
        const int row = gg * H_DIM + u;
        const float* Ws = W_ih_r + (l - 1) * 1600 + row * H_DIM;
        #pragma unroll
        for (int kk = 0; kk < 10; ++kk)
            wh[kk] = (unsigned long long)__float_as_uint(Ws[2 * kk] * sc) |
                     ((unsigned long long)__float_as_uint(Ws[2 * kk + 1] * sc) << 32);
        biash = (b_ih_r[(l - 1) * G4 + row] + b_hh_r[(l - 1) * G4 + row]) * sc;
    }
    const float lw = lane20 ? lin_w[jj] : 0.f;
    const float lb = lin_b[0];

    const float* gp = g_proj;   // [t][20 float4 rows of 4]

    // prologue A: mains' lanes >= 20 fill bias rows (constant thereafter)
    if (is_main && !lane20) {
        #pragma unroll
        for (int p2 = 0; p2 < 2; ++p2)
            #pragma unroll
            for (int i = 0; i < KSTEP; ++i)
                *(float4*)&pre[p2][l][i][j][0] =
                    make_float4(bias4[0], bias4[1], bias4[2], bias4[3]);
    }
    // prologue B: helper 0 stages block 0
    if (!is_main && l == 0 && lane20) {
        #pragma unroll
        for (int i = 0; i < KSTEP; ++i) {
            float4 v = __ldg((const float4*)&gp[(size_t)i * G4 + jj * 4]);
            *(float4*)&pre[0][0][i][jj][0] = v;
        }
    }
    float c = 0.f;
    float hlast = 0.f;
    __syncthreads();

    const unsigned FULL = 0xffffffffu;

    for (int k = 0; k < NPHASE; ++k) {
        const int p = k & 1;

        if (is_main) {
            const int b  = k - 2 * l;
            const int mv = k + 1 - 2 * l;
            const bool bval = (b >= 0) && (b < NB);
            const bool mval = (mv >= 0) && (mv < NB) && (l > 0);
            if (bval || mval) {
                #pragma unroll
                for (int i = 0; i < KSTEP; ++i) {
                    const float4 pr = *(const float4*)&pre[p][l][i][j][0];
                    unsigned long long ax[4], ay[4];
                    ax[0] = pack1(pr.x);
                    ax[1] = pack1(pr.y);
                    ax[2] = pack1(pr.z);
                    ax[3] = pack1(pr.w);
                    ay[0] = ay[1] = ay[2] = ay[3] = 0ull;
                    const ulonglong2* vp = lane20
                        ? (const ulonglong2*)&hb[l][0]
                        : (const ulonglong2*)&hx[p ^ 1][lm1][i][0];
                    #pragma unroll
                    for (int q = 0; q < 5; ++q) {
                        const ulonglong2 vv = vp[q];
                        #pragma unroll
                        for (int g = 0; g < 4; ++g) {
                            ax[g] = fma2(wv[g][2 * q],     vv.x, ax[g]);
                            ay[g] = fma2(wv[g][2 * q + 1], vv.y, ay[g]);
                        }
                    }
                    float gv[4];
                    #pragma unroll
                    for (int g = 0; g < 4; ++g) {
                        const unsigned long long s = add2(ax[g], ay[g]);
                        gv[g] = lo32(s) + hi32(s);
                    }
                    // activations (sig inputs pre-scaled by 0.5)
                    const float fi = fmaf(tanh_fast(gv[0]), 0.5f, 0.5f);
                    const float ff = fmaf(tanh_fast(gv[1]), 0.5f, 0.5f);
                    const float fg = tanh_fast(gv[2]);
                    const float fo = fmaf(tanh_fast(gv[3]), 0.5f, 0.5f);
                    const float nc = fmaf(ff, c, fi * fg);
                    const float nh = fo * tanh_fast(nc);

                    const bool upd = lane20 & bval;
                    c     = upd ? nc : c;
                    hlast = upd ? nh : hlast;
                    st_pred(upd, &hb[l][j], nh);
                    st_pred(upd & (l < 3), &hx[p][l][i][j], nh);
                    st4_pred((!lane20) & mval, &pre[p ^ 1][l][i][ujj][0],
                             gv[0], gv[1], gv[2], gv[3]);
                }
                if (l == 3 && b == NB - 1) {
                    float part = hlast * lw;   // lw = 0 for lanes >= 20
                    #pragma unroll
                    for (int off = 16; off; off >>= 1)
                        part += __shfl_xor_sync(FULL, part, off);
                    if (j == 0) out[0] = sig_fast(part + lb);
                }
            }
        } else if (l == 0) {
            const int m = k + 1;
            if (m < NB && lane20) {
                #pragma unroll
                for (int i = 0; i < KSTEP; ++i) {
                    float4 v = __ldg((const float4*)
                        &gp[((size_t)m * KSTEP + i) * G4 + jj * 4]);
                    *(float4*)&pre[p ^ 1][0][i][jj][0] = v;
                }
            }
        } else {
            const int m = k + 1 - 2 * l;
            if (m >= 0 && m < NB) {
                const int u  = 12 + (j >> 2);
                const int gg = j & 3;
                #pragma unroll
                for (int i = 0; i < KSTEP; ++i) {
                    const unsigned long long* vp =
                        (const unsigned long long*)&hx[p ^ 1][l - 1][i][0];
                    unsigned long long acc = pack1(biash);
                    #pragma unroll
                    for (int q = 0; q < 10; ++q)
                        acc = fma2(wh[q], vp[q], acc);
                    pre[p ^ 1][l][i][u][gg] = lo32(acc) + hi32(acc);
                }
            }
        }

        __syncthreads();   // orders pre/hx handoff between phases
    }
}

// ---------------------------------------------------------------------------
extern "C" void kernel_launch(void* const* d_in, const int* in_sizes, int n_in,
                              void* d_out, int out_size)
{
    const float* x      = (const float*)d_in[0];
    const float* W_ih0  = (const float*)d_in[1];
    const float* W_hh0  = (const float*)d_in[2];
    const float* b_ih0  = (const float*)d_in[3];
    const float* b_hh0  = (const float*)d_in[4];
    const float* W_ih_r = (const float*)d_in[5];
    const float* W_hh_r = (const float*)d_in[6];
    const float* b_ih_r = (const float*)d_in[7];
    const float* b_hh_r = (const float*)d_in[8];
    const float* lin_w  = (const float*)d_in[9];
    const float* lin_b  = (const float*)d_in[10];

    proj_kernel<<<T_SEQ / 8, 160>>>(x, W_ih0, b_ih0, b_hh0);
    rnn_kernel<<<1, 256>>>(W_hh0, W_ih_r, W_hh_r, b_ih_r, b_hh_r,
                           lin_w, lin_b, (float*)d_out);
}

// round 16
// speedup vs baseline: 3.1202x; 1.0003x over previous
#include <cuda_runtime.h>
#include <cuda_bf16.h>
#include <stdint.h>

#define T_SEQ   32768
#define IN_DIM  1024
#define H_DIM   20
#define NLAYER  4
#define G4      80
#define KSTEP   8
#define NB      (T_SEQ / KSTEP)
#define NPHASE  (NB + 2 * (NLAYER - 1))

// Layer-0 input projection, layout [t][unit][gate], sigmoid rows pre-scaled
// by 0.5 (both biases folded). 10.5 MB
__device__ float g_proj[T_SEQ * G4];

// ---------------------------------------------------------------------------
// Kernel 1: proj = (x @ W_ih0^T + b_ih0 + b_hh0) * sc(gate), [t][unit*4+gate]
// sc = 0.5 for sigmoid gates (i,f,o), 1.0 for tanh gate (g).
// ---------------------------------------------------------------------------
__global__ __launch_bounds__(160) void proj_kernel(
    const float* __restrict__ x,
    const float* __restrict__ W,
    const float* __restrict__ bi,
    const float* __restrict__ bh)
{
    __shared__ __align__(16) float xs[8 * IN_DIM];
    const int t0 = blockIdx.x * 8;

    const float4* xg  = (const float4*)(x + (size_t)t0 * IN_DIM);
    float4*       xs4 = (float4*)xs;
    for (int i = threadIdx.x; i < 8 * (IN_DIM / 4); i += blockDim.x)
        xs4[i] = xg[i];
    __syncthreads();

    const int tid = threadIdx.x;
    if (tid >= 160) return;
    const int g  = tid % 80;            // weight row: gate = g/20, unit = g%20
    const int th = tid / 80;
    const int didx = (g % 20) * 4 + (g / 20);
    const float sc = ((g / 20) == 2) ? 1.0f : 0.5f;

    const float4* Wg = (const float4*)(W + (size_t)g * IN_DIM);
    float a0 = 0.f, a1 = 0.f, a2 = 0.f, a3 = 0.f;

    #pragma unroll 4
    for (int kk = 0; kk < IN_DIM / 4; ++kk) {
        float4 w4 = Wg[kk];
        float4 v0 = xs4[(th * 4 + 0) * (IN_DIM / 4) + kk];
        float4 v1 = xs4[(th * 4 + 1) * (IN_DIM / 4) + kk];
        float4 v2 = xs4[(th * 4 + 2) * (IN_DIM / 4) + kk];
        float4 v3 = xs4[(th * 4 + 3) * (IN_DIM / 4) + kk];
        a0 = fmaf(w4.x, v0.x, a0); a0 = fmaf(w4.y, v0.y, a0);
        a0 = fmaf(w4.z, v0.z, a0); a0 = fmaf(w4.w, v0.w, a0);
        a1 = fmaf(w4.x, v1.x, a1); a1 = fmaf(w4.y, v1.y, a1);
        a1 = fmaf(w4.z, v1.z, a1); a1 = fmaf(w4.w, v1.w, a1);
        a2 = fmaf(w4.x, v2.x, a2); a2 = fmaf(w4.y, v2.y, a2);
        a2 = fmaf(w4.z, v2.z, a2); a2 = fmaf(w4.w, v2.w, a2);
        a3 = fmaf(w4.x, v3.x, a3); a3 = fmaf(w4.y, v3.y, a3);
        a3 = fmaf(w4.z, v3.z, a3); a3 = fmaf(w4.w, v3.w, a3);
    }

    const float b = bi[g] + bh[g];
    const int tb = t0 + th * 4;
    g_proj[(size_t)(tb + 0) * G4 + didx] = (a0 + b) * sc;
    g_proj[(size_t)(tb + 1) * G4 + didx] = (a1 + b) * sc;
    g_proj[(size_t)(tb + 2) * G4 + didx] = (a2 + b) * sc;
    g_proj[(size_t)(tb + 3) * G4 + didx] = (a3 + b) * sc;
}

// ---------------------------------------------------------------------------
__device__ __forceinline__ unsigned long long fma2(
    unsigned long long a, unsigned long long b, unsigned long long c)
{
    unsigned long long d;
    asm("fma.rn.f32x2 %0, %1, %2, %3;" : "=l"(d) : "l"(a), "l"(b), "l"(c));
    return d;
}
__device__ __forceinline__ unsigned long long add2(
    unsigned long long a, unsigned long long b)
{
    unsigned long long d;
    asm("add.rn.f32x2 %0, %1, %2;" : "=l"(d) : "l"(a), "l"(b));
    return d;
}
__device__ __forceinline__ float lo32(unsigned long long u) {
    return __uint_as_float((unsigned)u);
}
__device__ __forceinline__ float hi32(unsigned long long u) {
    return __uint_as_float((unsigned)(u >> 32));
}
__device__ __forceinline__ unsigned long long pack1(float lo) {
    return (unsigned long long)__float_as_uint(lo);   // (lo, 0.0f)
}
__device__ __forceinline__ float tanh_fast(float x) {
    float y;
    asm("tanh.approx.f32 %0, %1;" : "=f"(y) : "f"(x));
    return y;
}
__device__ __forceinline__ float sig_fast(float x) {
    return fmaf(tanh_fast(0.5f * x), 0.5f, 0.5f);
}
// predicated stores (no BSSY/BSYNC divergence penalty)
__device__ __forceinline__ void st_pred(bool pG, float* addr, float v) {
    asm volatile(
        "{ .reg .pred p; setp.ne.u32 p, %0, 0; @p st.f32 [%1], %2; }"
        :: "r"((int)pG), "l"(addr), "f"(v) : "memory");
}
__device__ __forceinline__ void st4_pred(bool pG, float* addr,
                                         float a, float b, float c, float d) {
    asm volatile(
        "{ .reg .pred p; setp.ne.u32 p, %0, 0; @p st.v4.f32 [%1], {%2,%3,%4,%5}; }"
        :: "r"((int)pG), "l"(addr), "f"(a), "f"(b), "f"(c), "f"(d) : "memory");
}

// ---------------------------------------------------------------------------
// Kernel 2: block-pipelined, branchless inner loop, gate-staged dataflow.
//  MAINS wid 4..7 (highest arbiter priority), layer l = wid-4; phase k ->
//  block b = k-2l. lanes 0..19 own-h recurrence; lanes 20..31 input dots for
//  block b+1 (same fma2 stream, bias rows 20..31 of pre).
//  Gate order: {i,f,g} dots first (their tanhs overlap the o-gate dot issue),
//  o last; tanh(nc) overlaps fo's dot+tanh.
//  HELPERS wid 0..3: units 12..19 input dots (l>0) / g_proj stager (l=0).
// Sigmoid-path weights pre-scaled by 0.5: sig = fma(tanh(acc),.5,.5).
// ONE __syncthreads per phase orders all pre/hx handoff (parity buffers).
// ---------------------------------------------------------------------------
__global__ __launch_bounds__(256, 1) void rnn_kernel(
    const float* __restrict__ W_hh0,   // [80][20]
    const float* __restrict__ W_ih_r,  // [3][80][20]
    const float* __restrict__ W_hh_r,  // [3][80][20]
    const float* __restrict__ b_ih_r,  // [3][80]
    const float* __restrict__ b_hh_r,  // [3][80]
    const float* __restrict__ lin_w,   // [20]
    const float* __restrict__ lin_b,   // [1]
    float* __restrict__ out)
{
    const int tid = threadIdx.x;
    const int wid = tid >> 5;
    const int j   = tid & 31;
    const int jj  = (j < H_DIM) ? j : H_DIM - 1;
    const bool lane20 = (j < H_DIM);
    const int ujj = lane20 ? 0 : (j - H_DIM);   // store unit for lanes >= 20

    // pre: 32 unit-rows; rows 20..31 are constant bias rows after prologue.
    __shared__ __align__(16) float pre[2][NLAYER][KSTEP][32][4];   // 32 KB
    __shared__ __align__(16) float hx [2][NLAYER][KSTEP][24];      // 6 KB
    __shared__ __align__(16) float hb [NLAYER][24];

    for (int i = tid; i < NLAYER * 24; i += blockDim.x)
        ((float*)hb)[i] = 0.f;
    for (int i = tid; i < 2 * NLAYER * KSTEP * 24; i += blockDim.x)
        ((float*)hx)[i] = 0.f;

    const bool is_main = (wid >= NLAYER);   // mains on high wids
    const int  l       = wid & 3;
    const int  lm1     = (l > 0) ? (l - 1) : 0;

    // ---- weights (sigmoid rows pre-scaled by 0.5) ----
    unsigned long long wv[4][10];
    unsigned long long wh[10];
    float bias4[4] = {0.f, 0.f, 0.f, 0.f};
    float biash = 0.f;
    #pragma unroll
    for (int g = 0; g < 4; ++g)
        #pragma unroll
        for (int kk = 0; kk < 10; ++kk) wv[g][kk] = 0ull;
    #pragma unroll
    for (int kk = 0; kk < 10; ++kk) wh[kk] = 0ull;

    if (is_main) {
        if (lane20) {
            #pragma unroll
            for (int g = 0; g < 4; ++g) {
                const float sc = (g == 2) ? 1.0f : 0.5f;
                const int row = g * H_DIM + j;
                const float* Ws = (l == 0) ? (W_hh0 + row * H_DIM)
                                           : (W_hh_r + (l - 1) * 1600 + row * H_DIM);
                #pragma unroll
                for (int kk = 0; kk < 10; ++kk)
                    wv[g][kk] = (unsigned long long)__float_as_uint(Ws[2 * kk] * sc) |
                                ((unsigned long long)__float_as_uint(Ws[2 * kk + 1] * sc) << 32);
            }
        } else if (l > 0) {
            const int u = j - H_DIM;
            #pragma unroll
            for (int g = 0; g < 4; ++g) {
                const float sc = (g == 2) ? 1.0f : 0.5f;
                const int row = g * H_DIM + u;
                const float* Ws = W_ih_r + (l - 1) * 1600 + row * H_DIM;
                #pragma unroll
                for (int kk = 0; kk < 10; ++kk)
                    wv[g][kk] = (unsigned long long)__float_as_uint(Ws[2 * kk] * sc) |
                                ((unsigned long long)__float_as_uint(Ws[2 * kk + 1] * sc) << 32);
                bias4[g] = (b_ih_r[(l - 1) * G4 + row] + b_hh_r[(l - 1) * G4 + row]) * sc;
            }
        }
    } else if (l > 0) {
        const int u  = 12 + (j >> 2);
        const int gg = j & 3;
        const float sc = (gg == 2) ? 1.0f : 0.5f;
        const int row = gg * H_DIM + u;
        const float* Ws = W_ih_r + (l - 1) * 1600 + row * H_DIM;
        #pragma unroll
        for (int kk = 0; kk < 10; ++kk)
            wh[kk] = (unsigned long long)__float_as_uint(Ws[2 * kk] * sc) |
                     ((unsigned long long)__float_as_uint(Ws[2 * kk + 1] * sc) << 32);
        biash = (b_ih_r[(l - 1) * G4 + row] + b_hh_r[(l - 1) * G4 + row]) * sc;
    }
    const float lw = lane20 ? lin_w[jj] : 0.f;
    const float lb = lin_b[0];

    const float* gp = g_proj;   // [t][20 rows of 4]

    // prologue A: mains' lanes >= 20 fill bias rows (constant thereafter)
    if (is_main && !lane20) {
        #pragma unroll
        for (int p2 = 0; p2 < 2; ++p2)
            #pragma unroll
            for (int i = 0; i < KSTEP; ++i)
                *(float4*)&pre[p2][l][i][j][0] =
                    make_float4(bias4[0], bias4[1], bias4[2], bias4[3]);
    }
    // prologue B: helper 0 stages block 0
    if (!is_main && l == 0 && lane20) {
        #pragma unroll
        for (int i = 0; i < KSTEP; ++i) {
            float4 v = __ldg((const float4*)&gp[(size_t)i * G4 + jj * 4]);
            *(float4*)&pre[0][0][i][jj][0] = v;
        }
    }
    float c = 0.f;
    float hlast = 0.f;
    __syncthreads();

    const unsigned FULL = 0xffffffffu;

    for (int k = 0; k < NPHASE; ++k) {
        const int p = k & 1;

        if (is_main) {
            const int b  = k - 2 * l;
            const int mv = k + 1 - 2 * l;
            const bool bval = (b >= 0) && (b < NB);
            const bool mval = (mv >= 0) && (mv < NB) && (l > 0);
            if (bval || mval) {
                #pragma unroll
                for (int i = 0; i < KSTEP; ++i) {
                    const float4 pr = *(const float4*)&pre[p][l][i][j][0];
                    const ulonglong2* vp = lane20
                        ? (const ulonglong2*)&hb[l][0]
                        : (const ulonglong2*)&hx[p ^ 1][lm1][i][0];
                    // hoist all operand pairs into registers
                    const ulonglong2 v0 = vp[0], v1 = vp[1], v2 = vp[2],
                                     v3 = vp[3], v4 = vp[4];

                    // ---- stage 1: gates i, f, g (30 fma2) ----
                    unsigned long long a0x = pack1(pr.x), a0y = 0ull;
                    unsigned long long a1x = pack1(pr.y), a1y = 0ull;
                    unsigned long long a2x = pack1(pr.z), a2y = 0ull;
                    a0x = fma2(wv[0][0], v0.x, a0x); a0y = fma2(wv[0][1], v0.y, a0y);
                    a1x = fma2(wv[1][0], v0.x, a1x); a1y = fma2(wv[1][1], v0.y, a1y);
                    a2x = fma2(wv[2][0], v0.x, a2x); a2y = fma2(wv[2][1], v0.y, a2y);
                    a0x = fma2(wv[0][2], v1.x, a0x); a0y = fma2(wv[0][3], v1.y, a0y);
                    a1x = fma2(wv[1][2], v1.x, a1x); a1y = fma2(wv[1][3], v1.y, a1y);
                    a2x = fma2(wv[2][2], v1.x, a2x); a2y = fma2(wv[2][3], v1.y, a2y);
                    a0x = fma2(wv[0][4], v2.x, a0x); a0y = fma2(wv[0][5], v2.y, a0y);
                    a1x = fma2(wv[1][4], v2.x, a1x); a1y = fma2(wv[1][5], v2.y, a1y);
                    a2x = fma2(wv[2][4], v2.x, a2x); a2y = fma2(wv[2][5], v2.y, a2y);
                    a0x = fma2(wv[0][6], v3.x, a0x); a0y = fma2(wv[0][7], v3.y, a0y);
                    a1x = fma2(wv[1][6], v3.x, a1x); a1y = fma2(wv[1][7], v3.y, a1y);
                    a2x = fma2(wv[2][6], v3.x, a2x); a2y = fma2(wv[2][7], v3.y, a2y);
                    a0x = fma2(wv[0][8], v4.x, a0x); a0y = fma2(wv[0][9], v4.y, a0y);
                    a1x = fma2(wv[1][8], v4.x, a1x); a1y = fma2(wv[1][9], v4.y, a1y);
                    a2x = fma2(wv[2][8], v4.x, a2x); a2y = fma2(wv[2][9], v4.y, a2y);
                    const unsigned long long s0 = add2(a0x, a0y);
                    const unsigned long long s1 = add2(a1x, a1y);
                    const unsigned long long s2 = add2(a2x, a2y);
                    const float gv0 = lo32(s0) + hi32(s0);
                    const float gv1 = lo32(s1) + hi32(s1);
                    const float gv2 = lo32(s2) + hi32(s2);
                    // tanhs of i,f,g start here; overlap o-gate issue below
                    const float fi = fmaf(tanh_fast(gv0), 0.5f, 0.5f);
                    const float ff = fmaf(tanh_fast(gv1), 0.5f, 0.5f);
                    const float fg = tanh_fast(gv2);

                    // ---- stage 2: gate o (10 fma2), overlapped ----
                    unsigned long long a3x = pack1(pr.w), a3y = 0ull;
                    a3x = fma2(wv[3][0], v0.x, a3x); a3y = fma2(wv[3][1], v0.y, a3y);
                    a3x = fma2(wv[3][2], v1.x, a3x); a3y = fma2(wv[3][3], v1.y, a3y);
                    a3x = fma2(wv[3][4], v2.x, a3x); a3y = fma2(wv[3][5], v2.y, a3y);
                    a3x = fma2(wv[3][6], v3.x, a3x); a3y = fma2(wv[3][7], v3.y, a3y);
                    a3x = fma2(wv[3][8], v4.x, a3x); a3y = fma2(wv[3][9], v4.y, a3y);

                    // nc / tanh(nc) overlap o-gate tail + its tanh
                    const float nc  = fmaf(ff, c, fi * fg);
                    const float tnc = tanh_fast(nc);

                    const unsigned long long s3 = add2(a3x, a3y);
                    const float gv3 = lo32(s3) + hi32(s3);
                    const float fo  = fmaf(tanh_fast(gv3), 0.5f, 0.5f);
                    const float nh  = fo * tnc;

                    const bool upd = lane20 & bval;
                    c     = upd ? nc : c;
                    hlast = upd ? nh : hlast;
                    st_pred(upd, &hb[l][j], nh);
                    st_pred(upd & (l < 3), &hx[p][l][i][j], nh);
                    st4_pred((!lane20) & mval, &pre[p ^ 1][l][i][ujj][0],
                             gv0, gv1, gv2, gv3);
                }
                if (l == 3 && b == NB - 1) {
                    float part = hlast * lw;   // lw = 0 for lanes >= 20
                    #pragma unroll
                    for (int off = 16; off; off >>= 1)
                        part += __shfl_xor_sync(FULL, part, off);
                    if (j == 0) out[0] = sig_fast(part + lb);
                }
            }
        } else if (l == 0) {
            const int m = k + 1;
            if (m < NB && lane20) {
                #pragma unroll
                for (int i = 0; i < KSTEP; ++i) {
                    float4 v = __ldg((const float4*)
                        &gp[((size_t)m * KSTEP + i) * G4 + jj * 4]);
                    *(float4*)&pre[p ^ 1][0][i][jj][0] = v;
                }
            }
        } else {
            const int m = k + 1 - 2 * l;
            if (m >= 0 && m < NB) {
                const int u  = 12 + (j >> 2);
                const int gg = j & 3;
                #pragma unroll
                for (int i = 0; i < KSTEP; ++i) {
                    const unsigned long long* vp =
                        (const unsigned long long*)&hx[p ^ 1][l - 1][i][0];
                    unsigned long long acc = pack1(biash);
                    #pragma unroll
                    for (int q = 0; q < 10; ++q)
                        acc = fma2(wh[q], vp[q], acc);
                    pre[p ^ 1][l][i][u][gg] = lo32(acc) + hi32(acc);
                }
            }
        }

        __syncthreads();   // orders pre/hx handoff between phases
    }
}

// ---------------------------------------------------------------------------
extern "C" void kernel_launch(void* const* d_in, const int* in_sizes, int n_in,
                              void* d_out, int out_size)
{
    const float* x      = (const float*)d_in[0];
    const float* W_ih0  = (const float*)d_in[1];
    const float* W_hh0  = (const float*)d_in[2];
    const float* b_ih0  = (const float*)d_in[3];
    const float* b_hh0  = (const float*)d_in[4];
    const float* W_ih_r = (const float*)d_in[5];
    const float* W_hh_r = (const float*)d_in[6];
    const float* b_ih_r = (const float*)d_in[7];
    const float* b_hh_r = (const float*)d_in[8];
    const float* lin_w  = (const float*)d_in[9];
    const float* lin_b  = (const float*)d_in[10];

    proj_kernel<<<T_SEQ / 8, 160>>>(x, W_ih0, b_ih0, b_hh0);
    rnn_kernel<<<1, 256>>>(W_hh0, W_ih_r, W_hh_r, b_ih_r, b_hh_r,
                           lin_w, lin_b, (float*)d_out);
}

// round 17
// speedup vs baseline: 3.1956x; 1.0242x over previous
#include <cuda_runtime.h>
#include <cuda_bf16.h>
#include <stdint.h>

#define T_SEQ   32768
#define IN_DIM  1024
#define H_DIM   20
#define NLAYER  4
#define G4      80
#define KSTEP   8
#define NB      (T_SEQ / KSTEP)
#define NPHASE  (NB + 2 * (NLAYER - 1))

// Layer-0 input projection, layout [t][unit][gate], sigmoid rows pre-scaled
// by 0.5 (both biases folded). 10.5 MB
__device__ float g_proj[T_SEQ * G4];

// ---------------------------------------------------------------------------
// Kernel 1: proj = (x @ W_ih0^T + b_ih0 + b_hh0) * sc(gate), [t][unit*4+gate]
// sc = 0.5 for sigmoid gates (i,f,o), 1.0 for tanh gate (g).
// ---------------------------------------------------------------------------
__global__ __launch_bounds__(160) void proj_kernel(
    const float* __restrict__ x,
    const float* __restrict__ W,
    const float* __restrict__ bi,
    const float* __restrict__ bh)
{
    __shared__ __align__(16) float xs[8 * IN_DIM];
    const int t0 = blockIdx.x * 8;

    const float4* xg  = (const float4*)(x + (size_t)t0 * IN_DIM);
    float4*       xs4 = (float4*)xs;
    for (int i = threadIdx.x; i < 8 * (IN_DIM / 4); i += blockDim.x)
        xs4[i] = xg[i];
    __syncthreads();

    const int tid = threadIdx.x;
    if (tid >= 160) return;
    const int g  = tid % 80;            // weight row: gate = g/20, unit = g%20
    const int th = tid / 80;
    const int didx = (g % 20) * 4 + (g / 20);
    const float sc = ((g / 20) == 2) ? 1.0f : 0.5f;

    const float4* Wg = (const float4*)(W + (size_t)g * IN_DIM);
    float a0 = 0.f, a1 = 0.f, a2 = 0.f, a3 = 0.f;

    #pragma unroll 4
    for (int kk = 0; kk < IN_DIM / 4; ++kk) {
        float4 w4 = Wg[kk];
        float4 v0 = xs4[(th * 4 + 0) * (IN_DIM / 4) + kk];
        float4 v1 = xs4[(th * 4 + 1) * (IN_DIM / 4) + kk];
        float4 v2 = xs4[(th * 4 + 2) * (IN_DIM / 4) + kk];
        float4 v3 = xs4[(th * 4 + 3) * (IN_DIM / 4) + kk];
        a0 = fmaf(w4.x, v0.x, a0); a0 = fmaf(w4.y, v0.y, a0);
        a0 = fmaf(w4.z, v0.z, a0); a0 = fmaf(w4.w, v0.w, a0);
        a1 = fmaf(w4.x, v1.x, a1); a1 = fmaf(w4.y, v1.y, a1);
        a1 = fmaf(w4.z, v1.z, a1); a1 = fmaf(w4.w, v1.w, a1);
        a2 = fmaf(w4.x, v2.x, a2); a2 = fmaf(w4.y, v2.y, a2);
        a2 = fmaf(w4.z, v2.z, a2); a2 = fmaf(w4.w, v2.w, a2);
        a3 = fmaf(w4.x, v3.x, a3); a3 = fmaf(w4.y, v3.y, a3);
        a3 = fmaf(w4.z, v3.z, a3); a3 = fmaf(w4.w, v3.w, a3);
    }

    const float b = bi[g] + bh[g];
    const int tb = t0 + th * 4;
    g_proj[(size_t)(tb + 0) * G4 + didx] = (a0 + b) * sc;
    g_proj[(size_t)(tb + 1) * G4 + didx] = (a1 + b) * sc;
    g_proj[(size_t)(tb + 2) * G4 + didx] = (a2 + b) * sc;
    g_proj[(size_t)(tb + 3) * G4 + didx] = (a3 + b) * sc;
}

// ---------------------------------------------------------------------------
__device__ __forceinline__ unsigned long long fma2(
    unsigned long long a, unsigned long long b, unsigned long long c)
{
    unsigned long long d;
    asm("fma.rn.f32x2 %0, %1, %2, %3;" : "=l"(d) : "l"(a), "l"(b), "l"(c));
    return d;
}
__device__ __forceinline__ float lo32(unsigned long long u) {
    return __uint_as_float((unsigned)u);
}
__device__ __forceinline__ float hi32(unsigned long long u) {
    return __uint_as_float((unsigned)(u >> 32));
}
__device__ __forceinline__ unsigned long long pack1(float lo) {
    return (unsigned long long)__float_as_uint(lo);   // (lo, 0.0f)
}
__device__ __forceinline__ float tanh_fast(float x) {
    float y;
    asm("tanh.approx.f32 %0, %1;" : "=f"(y) : "f"(x));
    return y;
}
__device__ __forceinline__ float sig_fast(float x) {
    return fmaf(tanh_fast(0.5f * x), 0.5f, 0.5f);
}

// ---------------------------------------------------------------------------
// Kernel 2: block-pipelined, branchless inner loop, minimal instruction count.
//  MAINS wid 4..7 (highest arbiter priority), layer l = wid-4; phase k ->
//  block b = k-2l. lanes 0..19 own-h recurrence; lanes 20..31 input dots for
//  block b+1 (same fma2 stream; bias rows 20..31 of pre).
//  HELPERS wid 0..3: units 12..19 input dots (l>0) / g_proj stager (l=0).
//  Per-gate dot = ONE 10-deep fma2 chain (no add2 merge). All inner-loop
//  stores are UNCONDITIONAL to per-phase-selected destinations (real target
//  or smem dummy sink, stride 0 for dummy) -> zero setp/predication in loop.
// Sigmoid-path weights pre-scaled by 0.5: sig = fma(tanh(acc),.5,.5).
// ONE __syncthreads per phase orders all pre/hx handoff (parity buffers).
// ---------------------------------------------------------------------------
__global__ __launch_bounds__(256, 1) void rnn_kernel(
    const float* __restrict__ W_hh0,   // [80][20]
    const float* __restrict__ W_ih_r,  // [3][80][20]
    const float* __restrict__ W_hh_r,  // [3][80][20]
    const float* __restrict__ b_ih_r,  // [3][80]
    const float* __restrict__ b_hh_r,  // [3][80]
    const float* __restrict__ lin_w,   // [20]
    const float* __restrict__ lin_b,   // [1]
    float* __restrict__ out)
{
    const int tid = threadIdx.x;
    const int wid = tid >> 5;
    const int j   = tid & 31;
    const int jj  = (j < H_DIM) ? j : H_DIM - 1;
    const bool lane20 = (j < H_DIM);
    const int ujj = lane20 ? 0 : (j - H_DIM);   // store unit for lanes >= 20

    // pre: 32 unit-rows; rows 20..31 are constant bias rows after prologue.
    __shared__ __align__(16) float pre[2][NLAYER][KSTEP][32][4];   // 32 KB
    __shared__ __align__(16) float hx [2][NLAYER][KSTEP][24];      // 6 KB
    __shared__ __align__(16) float hb [NLAYER][24];
    __shared__ __align__(16) float sink[160];                      // dummy dst

    for (int i = tid; i < NLAYER * 24; i += blockDim.x)
        ((float*)hb)[i] = 0.f;
    for (int i = tid; i < 2 * NLAYER * KSTEP * 24; i += blockDim.x)
        ((float*)hx)[i] = 0.f;

    const bool is_main = (wid >= NLAYER);   // mains on high wids
    const int  l       = wid & 3;
    const int  lm1     = (l > 0) ? (l - 1) : 0;

    // ---- weights (sigmoid rows pre-scaled by 0.5) ----
    unsigned long long wv[4][10];
    unsigned long long wh[10];
    float bias4[4] = {0.f, 0.f, 0.f, 0.f};
    float biash = 0.f;
    #pragma unroll
    for (int g = 0; g < 4; ++g)
        #pragma unroll
        for (int kk = 0; kk < 10; ++kk) wv[g][kk] = 0ull;
    #pragma unroll
    for (int kk = 0; kk < 10; ++kk) wh[kk] = 0ull;

    if (is_main) {
        if (lane20) {
            #pragma unroll
            for (int g = 0; g < 4; ++g) {
                const float sc = (g == 2) ? 1.0f : 0.5f;
                const int row = g * H_DIM + j;
                const float* Ws = (l == 0) ? (W_hh0 + row * H_DIM)
                                           : (W_hh_r + (l - 1) * 1600 + row * H_DIM);
                #pragma unroll
                for (int kk = 0; kk < 10; ++kk)
                    wv[g][kk] = (unsigned long long)__float_as_uint(Ws[2 * kk] * sc) |
                                ((unsigned long long)__float_as_uint(Ws[2 * kk + 1] * sc) << 32);
            }
        } else if (l > 0) {
            const int u = j - H_DIM;
            #pragma unroll
            for (int g = 0; g < 4; ++g) {
                const float sc = (g == 2) ? 1.0f : 0.5f;
                const int row = g * H_DIM + u;
                const float* Ws = W_ih_r + (l - 1) * 1600 + row * H_DIM;
                #pragma unroll
                for (int kk = 0; kk < 10; ++kk)
                    wv[g][kk] = (unsigned long long)__float_as_uint(Ws[2 * kk] * sc) |
                                ((unsigned long long)__float_as_uint(Ws[2 * kk + 1] * sc) << 32);
                bias4[g] = (b_ih_r[(l - 1) * G4 + row] + b_hh_r[(l - 1) * G4 + row]) * sc;
            }
        }
    } else if (l > 0) {
        const int u  = 12 + (j >> 2);
        const int gg = j & 3;
        const float sc = (gg == 2) ? 1.0f : 0.5f;
        const int row = gg * H_DIM + u;
        const float* Ws = W_ih_r + (l - 1) * 1600 + row * H_DIM;
        #pragma unroll
        for (int kk = 0; kk < 10; ++kk)
            wh[kk] = (unsigned long long)__float_as_uint(Ws[2 * kk] * sc) |
                     ((unsigned long long)__float_as_uint(Ws[2 * kk + 1] * sc) << 32);
        biash = (b_ih_r[(l - 1) * G4 + row] + b_hh_r[(l - 1) * G4 + row]) * sc;
    }
    const float lw = lane20 ? lin_w[jj] : 0.f;
    const float lb = lin_b[0];

    const float* gp = g_proj;   // [t][20 rows of 4]

    // prologue A: mains' lanes >= 20 fill bias rows (constant thereafter)
    if (is_main && !lane20) {
        #pragma unroll
        for (int p2 = 0; p2 < 2; ++p2)
            #pragma unroll
            for (int i = 0; i < KSTEP; ++i)
                *(float4*)&pre[p2][l][i][j][0] =
                    make_float4(bias4[0], bias4[1], bias4[2], bias4[3]);
    }
    // prologue B: helper 0 stages block 0
    if (!is_main && l == 0 && lane20) {
        #pragma unroll
        for (int i = 0; i < KSTEP; ++i) {
            float4 v = __ldg((const float4*)&gp[(size_t)i * G4 + jj * 4]);
            *(float4*)&pre[0][0][i][jj][0] = v;
        }
    }
    float c = 0.f;
    float hlast = 0.f;
    __syncthreads();

    const unsigned FULL = 0xffffffffu;

    for (int k = 0; k < NPHASE; ++k) {
        const int p = k & 1;

        if (is_main) {
            const int b  = k - 2 * l;
            const int mv = k + 1 - 2 * l;
            const bool bval = (b >= 0) && (b < NB);
            const bool mval = (mv >= 0) && (mv < NB) && (l > 0);
            if (bval || mval) {
                const bool upd = lane20 & bval;
                // per-phase destination select (sink = discard, stride 0)
                float* hb_dst  = upd ? &hb[l][j] : &sink[j];
                float* hx_base = (upd && l < 3) ? &hx[p][l][0][j] : &sink[j];
                const int hx_str = (upd && l < 3) ? 24 : 0;
                float* pre_base = ((!lane20) && mval)
                    ? &pre[p ^ 1][l][0][ujj][0] : &sink[32 + (j & 31) * 4];
                const int pre_str = ((!lane20) && mval) ? 128 : 0;

                #pragma unroll
                for (int i = 0; i < KSTEP; ++i) {
                    const float4 pr = *(const float4*)&pre[p][l][i][j][0];
                    const ulonglong2* vp = lane20
                        ? (const ulonglong2*)&hb[l][0]
                        : (const ulonglong2*)&hx[p ^ 1][lm1][i][0];
                    const ulonglong2 v0 = vp[0], v1 = vp[1], v2 = vp[2],
                                     v3 = vp[3], v4 = vp[4];

                    // one 10-deep fma2 chain per gate (4 independent chains)
                    unsigned long long a0 = pack1(pr.x);
                    unsigned long long a1 = pack1(pr.y);
                    unsigned long long a2 = pack1(pr.z);
                    unsigned long long a3 = pack1(pr.w);
                    a0 = fma2(wv[0][0], v0.x, a0); a1 = fma2(wv[1][0], v0.x, a1);
                    a2 = fma2(wv[2][0], v0.x, a2); a3 = fma2(wv[3][0], v0.x, a3);
                    a0 = fma2(wv[0][1], v0.y, a0); a1 = fma2(wv[1][1], v0.y, a1);
                    a2 = fma2(wv[2][1], v0.y, a2); a3 = fma2(wv[3][1], v0.y, a3);
                    a0 = fma2(wv[0][2], v1.x, a0); a1 = fma2(wv[1][2], v1.x, a1);
                    a2 = fma2(wv[2][2], v1.x, a2); a3 = fma2(wv[3][2], v1.x, a3);
                    a0 = fma2(wv[0][3], v1.y, a0); a1 = fma2(wv[1][3], v1.y, a1);
                    a2 = fma2(wv[2][3], v1.y, a2); a3 = fma2(wv[3][3], v1.y, a3);
                    a0 = fma2(wv[0][4], v2.x, a0); a1 = fma2(wv[1][4], v2.x, a1);
                    a2 = fma2(wv[2][4], v2.x, a2); a3 = fma2(wv[3][4], v2.x, a3);
                    a0 = fma2(wv[0][5], v2.y, a0); a1 = fma2(wv[1][5], v2.y, a1);
                    a2 = fma2(wv[2][5], v2.y, a2); a3 = fma2(wv[3][5], v2.y, a3);
                    a0 = fma2(wv[0][6], v3.x, a0); a1 = fma2(wv[1][6], v3.x, a1);
                    a2 = fma2(wv[2][6], v3.x, a2); a3 = fma2(wv[3][6], v3.x, a3);
                    a0 = fma2(wv[0][7], v3.y, a0); a1 = fma2(wv[1][7], v3.y, a1);
                    a2 = fma2(wv[2][7], v3.y, a2); a3 = fma2(wv[3][7], v3.y, a3);
                    a0 = fma2(wv[0][8], v4.x, a0); a1 = fma2(wv[1][8], v4.x, a1);
                    a2 = fma2(wv[2][8], v4.x, a2); a3 = fma2(wv[3][8], v4.x, a3);
                    a0 = fma2(wv[0][9], v4.y, a0); a1 = fma2(wv[1][9], v4.y, a1);
                    a2 = fma2(wv[2][9], v4.y, a2); a3 = fma2(wv[3][9], v4.y, a3);

                    const float gv0 = lo32(a0) + hi32(a0);
                    const float gv1 = lo32(a1) + hi32(a1);
                    const float gv2 = lo32(a2) + hi32(a2);
                    const float gv3 = lo32(a3) + hi32(a3);

                    const float fi = fmaf(tanh_fast(gv0), 0.5f, 0.5f);
                    const float ff = fmaf(tanh_fast(gv1), 0.5f, 0.5f);
                    const float fg = tanh_fast(gv2);
                    const float fo = fmaf(tanh_fast(gv3), 0.5f, 0.5f);
                    const float nc = fmaf(ff, c, fi * fg);
                    const float nh = fo * tanh_fast(nc);

                    c     = upd ? nc : c;
                    hlast = upd ? nh : hlast;
                    *hb_dst = nh;                       // unconditional
                    hx_base[i * hx_str] = nh;           // unconditional
                    *(float4*)&pre_base[i * pre_str] =  // unconditional
                        make_float4(gv0, gv1, gv2, gv3);
                }
                if (l == 3 && b == NB - 1) {
                    float part = hlast * lw;   // lw = 0 for lanes >= 20
                    #pragma unroll
                    for (int off = 16; off; off >>= 1)
                        part += __shfl_xor_sync(FULL, part, off);
                    if (j == 0) out[0] = sig_fast(part + lb);
                }
            }
        } else if (l == 0) {
            const int m = k + 1;
            if (m < NB && lane20) {
                #pragma unroll
                for (int i = 0; i < KSTEP; ++i) {
                    float4 v = __ldg((const float4*)
                        &gp[((size_t)m * KSTEP + i) * G4 + jj * 4]);
                    *(float4*)&pre[p ^ 1][0][i][jj][0] = v;
                }
            }
        } else {
            const int m = k + 1 - 2 * l;
            if (m >= 0 && m < NB) {
                const int u  = 12 + (j >> 2);
                const int gg = j & 3;
                #pragma unroll
                for (int i = 0; i < KSTEP; ++i) {
                    const ulonglong2* vp =
                        (const ulonglong2*)&hx[p ^ 1][l - 1][i][0];
                    const ulonglong2 w0 = vp[0], w1 = vp[1], w2 = vp[2],
                                     w3 = vp[3], w4 = vp[4];
                    unsigned long long acc = pack1(biash);
                    acc = fma2(wh[0], w0.x, acc);
                    acc = fma2(wh[1], w0.y, acc);
                    acc = fma2(wh[2], w1.x, acc);
                    acc = fma2(wh[3], w1.y, acc);
                    acc = fma2(wh[4], w2.x, acc);
                    acc = fma2(wh[5], w2.y, acc);
                    acc = fma2(wh[6], w3.x, acc);
                    acc = fma2(wh[7], w3.y, acc);
                    acc = fma2(wh[8], w4.x, acc);
                    acc = fma2(wh[9], w4.y, acc);
                    pre[p ^ 1][l][i][u][gg] = lo32(acc) + hi32(acc);
                }
            }
        }

        __syncthreads();   // orders pre/hx handoff between phases
    }
}

// ---------------------------------------------------------------------------
extern "C" void kernel_launch(void* const* d_in, const int* in_sizes, int n_in,
                              void* d_out, int out_size)
{
    const float* x      = (const float*)d_in[0];
    const float* W_ih0  = (const float*)d_in[1];
    const float* W_hh0  = (const float*)d_in[2];
    const float* b_ih0  = (const float*)d_in[3];
    const float* b_hh0  = (const float*)d_in[4];
    const float* W_ih_r = (const float*)d_in[5];
    const float* W_hh_r = (const float*)d_in[6];
    const float* b_ih_r = (const float*)d_in[7];
    const float* b_hh_r = (const float*)d_in[8];
    const float* lin_w  = (const float*)d_in[9];
    const float* lin_b  = (const float*)d_in[10];

    proj_kernel<<<T_SEQ / 8, 160>>>(x, W_ih0, b_ih0, b_hh0);
    rnn_kernel<<<1, 256>>>(W_hh0, W_ih_r, W_hh_r, b_ih_r, b_hh_r,
                           lin_w, lin_b, (float*)d_out);
}